// round 7
// baseline (speedup 1.0000x reference)
#include <cuda_runtime.h>
#include <cuda_fp16.h>

#define NN 50000
#define EE 800000
#define HH 128
#define GG 500
#define FC1 64
#define EPSBN 1e-5f
#define BLK 148
#define THR 512
#define NWARP 16
#define TOTW (BLK * NWARP)        /* 2368 warps */
#define SCHUNK 344                /* 148*344 = 50912 >= NN */

// ---------------- device scratch (static, no allocation) ----------------
__device__ __align__(16) unsigned g_h16u[NN * (HH / 2)];  // fp16 messages
__device__ float g_agg[NN * HH];
__device__ int   g_cnt[NN];
__device__ int   g_fill[NN];
__device__ int   g_ptr[NN + 1];
__device__ float g_dis[NN];
__device__ __align__(16) uint2 g_csr[EE];   // packed (src, w)
__device__ int   g_bsum[BLK];
__device__ int   g_boff[BLK];
__device__ float g_psC[BLK * HH];
__device__ float g_pqC[BLK * HH];
__device__ float g_bn_a[HH];
__device__ float g_bn_b[HH];
__device__ int   g_goff[GG + 1];
__device__ float g_z[GG * FC1];
__device__ float g_wh[3][HH * HH];
__device__ float g_wl[3][HH * HH];
__device__ unsigned g_barc;   // barrier arrival counter (reset by k_reset)
__device__ unsigned g_barr;   // barrier release epoch
__device__ int   g_is64;

// ---------------- helpers ----------------
__device__ __forceinline__ int ld_idx(const void* p, long long i, int is64) {
    return is64 ? (int)(((const long long*)p)[i]) : ((const int*)p)[i];
}

__device__ __forceinline__ unsigned f2tf32(float v) {
    unsigned o;
    asm("cvt.rna.tf32.f32 %0, %1;" : "=r"(o) : "f"(v));
    return o;
}

// grid barrier: monotonic counter + release epoch (reset by k_reset per launch)
__device__ __forceinline__ void gbar(int* ep) {
    __syncthreads();
    (*ep)++;
    if (threadIdx.x == 0) {
        __threadfence();
        unsigned n = atomicAdd(&g_barc, 1u) + 1u;
        if (n == (unsigned)(*ep) * BLK) atomicAdd(&g_barr, 1u);
        while (atomicAdd(&g_barr, 0u) < (unsigned)(*ep)) __nanosleep(64);
        __threadfence();
    }
    __syncthreads();
}

__global__ void k_reset() {
    g_barc = 0u;
    g_barr = 0u;
}

// ---------------- GEMM tile strides ----------------
#define XS_STRIDE 132
#define WS_STRIDE 136
#define GEMM_SMEM ((128 * XS_STRIDE + 2 * 128 * WS_STRIDE) * 4)
#define GEMM_TILES ((NN + 127) / 128)

// ---------------- the megakernel ----------------
__global__ void __launch_bounds__(THR, 1) k_mega(
    const float* __restrict__ x, const void* __restrict__ eidx,
    const void* __restrict__ batc,
    const float* __restrict__ W1, const float* __restrict__ b1,
    const float* __restrict__ g1, const float* __restrict__ be1,
    const float* __restrict__ W2, const float* __restrict__ b2,
    const float* __restrict__ g2, const float* __restrict__ be2,
    const float* __restrict__ W3, const float* __restrict__ b3,
    const float* __restrict__ g3, const float* __restrict__ be3,
    const float* __restrict__ fcW1, const float* __restrict__ fcb1,
    const float* __restrict__ fcg1, const float* __restrict__ fcbe1,
    const float* __restrict__ fcW2, const float* __restrict__ fcb2,
    float* __restrict__ out) {
    extern __shared__ float smem[];
    int ep = 0;
    int b = blockIdx.x;
    int t = threadIdx.x;
    int gid = b * THR + t;

    // ---------- P0: zero counters, dtype detect, W presplit ----------
    for (int i = gid; i < NN; i += BLK * THR) { g_cnt[i] = 0; g_fill[i] = 0; }
    // dtype detect: ALL threads of block 0 reach both __syncthreads
    // (guard only the load/atomic — divergent barriers here caused the R6 crash)
    if (b == 0) {
        __shared__ int any;
        if (t == 0) any = 0;
        __syncthreads();
        if (t < 256 && ((const int*)eidx)[2 * t + 1] != 0) atomicOr(&any, 1);
        __syncthreads();
        if (t == 0) g_is64 = any ? 0 : 1;
    }
    for (int i = gid; i < 3 * HH * HH; i += BLK * THR) {
        int k = i / (HH * HH);
        int j = i - k * (HH * HH);
        float w = (k == 0) ? W1[j] : (k == 1) ? W2[j] : W3[j];
        unsigned hi = f2tf32(w);
        g_wh[k][j] = __uint_as_float(hi);
        g_wl[k][j] = __uint_as_float(f2tf32(w - __uint_as_float(hi)));
    }
    gbar(&ep);  // 1

    // ---------- P1: edge histogram + graph bounds ----------
    {
        int is64 = g_is64;
        for (int e = gid; e < EE; e += BLK * THR) {
            int d = ld_idx(eidx, (long long)EE + e, is64);
            atomicAdd(&g_cnt[d], 1);
        }
        for (int i = gid; i < NN; i += BLK * THR) {
            int bb = ld_idx(batc, i, is64);
            int bn = (i + 1 < NN) ? ld_idx(batc, i + 1, is64) : GG;
            if (i == 0) {
                int hi0 = bb < GG ? bb : GG;
                for (int g = 0; g <= hi0; g++) g_goff[g] = 0;
            }
            int lo = bb + 1 > 0 ? bb + 1 : 0;
            int hi = bn < GG ? bn : GG;
            for (int g = lo; g <= hi; g++) g_goff[g] = i + 1;
        }
    }
    gbar(&ep);  // 2

    // ---------- P2: CSR scan (per-CTA chunk + 148-scan + apply) ----------
    int my_c = 0, my_lex = 0;
    {
        int* ism = (int*)smem;
        int i = b * SCHUNK + t;
        my_c = (t < SCHUNK && i < NN) ? g_cnt[i] : 0;
        ism[t] = my_c;
        __syncthreads();
        for (int off = 1; off < THR; off <<= 1) {
            int v = (t >= off) ? ism[t - off] : 0;
            __syncthreads();
            ism[t] += v;
            __syncthreads();
        }
        my_lex = ism[t] - my_c;
        if (t == 0) g_bsum[b] = ism[THR - 1];
    }
    gbar(&ep);  // 3
    if (b == 0) {
        int* ism = (int*)smem;
        int v = (t < BLK) ? g_bsum[t] : 0;
        __syncthreads();
        ism[t] = v;
        __syncthreads();
        for (int off = 1; off < THR; off <<= 1) {
            int u = (t >= off) ? ism[t - off] : 0;
            __syncthreads();
            ism[t] += u;
            __syncthreads();
        }
        if (t < BLK) g_boff[t] = ism[t] - v;
    }
    gbar(&ep);  // 4
    {
        int i = b * SCHUNK + t;
        if (t < SCHUNK && i < NN) {
            int ex = my_lex + g_boff[b];
            g_ptr[i] = ex;
            g_dis[i] = rsqrtf((float)(my_c + 1));
            if (i == NN - 1) g_ptr[NN] = ex + my_c;
        }
    }
    gbar(&ep);  // 5

    // ---------- P3: CSR fill (packed uint2) ----------
    {
        int is64 = g_is64;
        for (int e = gid; e < EE; e += BLK * THR) {
            int s = ld_idx(eidx, e, is64);
            int d = ld_idx(eidx, (long long)EE + e, is64);
            int pos = atomicAdd(&g_fill[d], 1);
            float w = g_dis[s] * g_dis[d];
            g_csr[g_ptr[d] + pos] = make_uint2((unsigned)s, __float_as_uint(w));
        }
    }
    gbar(&ep);  // 6

    // ---------- layers ----------
    int wid = t >> 5;
    int lane = t & 31;

    for (int L = 0; L < 3; L++) {
        const float* Xsrc = (L == 0) ? x : g_agg;
        const float* Wh = g_wh[L];
        const float* Wl = g_wl[L];
        const float* bias = (L == 0) ? b1 : (L == 1) ? b2 : b3;
        const float* gam = (L == 0) ? g1 : (L == 1) ? g2 : g3;
        const float* bet = (L == 0) ? be1 : (L == 1) ? be2 : be3;
        bool bn = (L > 0);

        // ===== GEMM phase: tiles b, b+148, ... =====
        {
            float* Xs = smem;
            float* Whs = Xs + 128 * XS_STRIDE;
            float* Wls = Whs + 128 * WS_STRIDE;
            int mwid = wid >> 2, nwid = wid & 3;
            int g = lane >> 2, tg = lane & 3;

            for (int tile = b; tile < GEMM_TILES; tile += BLK) {
                int row0 = tile * 128;
                __syncthreads();
                // X tile (fused BN+ReLU)
#pragma unroll
                for (int i = 0; i < 8; i++) {
                    int q = i * THR + t;
                    int r = q >> 5;
                    int c = (q & 31) * 4;
                    int gr = row0 + r;
                    float4 v = make_float4(0.f, 0.f, 0.f, 0.f);
                    if (gr < NN) v = *(const float4*)(Xsrc + (size_t)gr * 128 + c);
                    if (bn) {
                        v.x = fmaxf(g_bn_a[c + 0] * v.x + g_bn_b[c + 0], 0.f);
                        v.y = fmaxf(g_bn_a[c + 1] * v.y + g_bn_b[c + 1], 0.f);
                        v.z = fmaxf(g_bn_a[c + 2] * v.z + g_bn_b[c + 2], 0.f);
                        v.w = fmaxf(g_bn_a[c + 3] * v.w + g_bn_b[c + 3], 0.f);
                    }
                    *(float4*)(Xs + r * XS_STRIDE + c) = v;
                }
                // W hi/lo tiles
#pragma unroll
                for (int i = 0; i < 8; i++) {
                    int q = i * THR + t;
                    int r = q >> 5;
                    int c = (q & 31) * 4;
                    *(float4*)(Whs + r * WS_STRIDE + c) =
                        *(const float4*)(Wh + (size_t)r * 128 + c);
                    *(float4*)(Wls + r * WS_STRIDE + c) =
                        *(const float4*)(Wl + (size_t)r * 128 + c);
                }
                __syncthreads();

                float acc[2][4][4];
#pragma unroll
                for (int mi = 0; mi < 2; mi++)
#pragma unroll
                    for (int ni = 0; ni < 4; ni++)
#pragma unroll
                        for (int j = 0; j < 4; j++) acc[mi][ni][j] = 0.f;

#define SPLIT(V, HI, LO)                        \
    do {                                        \
        HI = f2tf32(V);                         \
        LO = f2tf32((V) - __uint_as_float(HI)); \
    } while (0)
#define MMA(A0, A1, A2, A3, B0, B1, C)                                  \
    asm volatile(                                                       \
        "mma.sync.aligned.m16n8k8.row.col.f32.tf32.tf32.f32 "           \
        "{%0,%1,%2,%3}, {%4,%5,%6,%7}, {%8,%9}, {%0,%1,%2,%3};"         \
        : "+f"(C[0]), "+f"(C[1]), "+f"(C[2]), "+f"(C[3])                \
        : "r"(A0), "r"(A1), "r"(A2), "r"(A3), "r"(B0), "r"(B1))

#pragma unroll
                for (int k0 = 0; k0 < 128; k0 += 8) {
                    unsigned ah[2][4], al[2][4];
#pragma unroll
                    for (int mi = 0; mi < 2; mi++) {
                        int rb = mwid * 32 + mi * 16;
                        int o0 = (rb + g) * XS_STRIDE + k0 + tg;
                        int o1 = (rb + g + 8) * XS_STRIDE + k0 + tg;
                        float v0 = Xs[o0], v1 = Xs[o1];
                        float v2 = Xs[o0 + 4], v3 = Xs[o1 + 4];
                        SPLIT(v0, ah[mi][0], al[mi][0]);
                        SPLIT(v1, ah[mi][1], al[mi][1]);
                        SPLIT(v2, ah[mi][2], al[mi][2]);
                        SPLIT(v3, ah[mi][3], al[mi][3]);
                    }
                    unsigned bh[4][2], bl[4][2];
#pragma unroll
                    for (int ni = 0; ni < 4; ni++) {
                        int cb = nwid * 32 + ni * 8;
                        int o0 = (k0 + tg) * WS_STRIDE + cb + g;
                        int o1 = (k0 + tg + 4) * WS_STRIDE + cb + g;
                        bh[ni][0] = __float_as_uint(Whs[o0]);
                        bh[ni][1] = __float_as_uint(Whs[o1]);
                        bl[ni][0] = __float_as_uint(Wls[o0]);
                        bl[ni][1] = __float_as_uint(Wls[o1]);
                    }
#pragma unroll
                    for (int mi = 0; mi < 2; mi++)
#pragma unroll
                        for (int ni = 0; ni < 4; ni++) {
                            MMA(ah[mi][0], ah[mi][1], ah[mi][2], ah[mi][3],
                                bh[ni][0], bh[ni][1], acc[mi][ni]);
                            MMA(ah[mi][0], ah[mi][1], ah[mi][2], ah[mi][3],
                                bl[ni][0], bl[ni][1], acc[mi][ni]);
                            MMA(al[mi][0], al[mi][1], al[mi][2], al[mi][3],
                                bh[ni][0], bh[ni][1], acc[mi][ni]);
                        }
                }
#undef MMA
#undef SPLIT

#pragma unroll
                for (int mi = 0; mi < 2; mi++) {
#pragma unroll
                    for (int ni = 0; ni < 4; ni++) {
                        int col = nwid * 32 + ni * 8 + tg * 2;
                        int r1 = row0 + mwid * 32 + mi * 16 + g;
                        int r2 = r1 + 8;
                        if (r1 < NN) {
                            __half2 h = __floats2half2_rn(acc[mi][ni][0],
                                                          acc[mi][ni][1]);
                            g_h16u[(size_t)r1 * 64 + (col >> 1)] = *(unsigned*)&h;
                        }
                        if (r2 < NN) {
                            __half2 h = __floats2half2_rn(acc[mi][ni][2],
                                                          acc[mi][ni][3]);
                            g_h16u[(size_t)r2 * 64 + (col >> 1)] = *(unsigned*)&h;
                        }
                    }
                }
            }
        }
        gbar(&ep);  // after gemm

        // ===== AGG phase: per-warp node loop + per-CTA stats =====
        {
            float* ps = smem;              // [16][128]
            float* pq = smem + NWARP * HH; // [16][128]
            const uint2* Hv = (const uint2*)g_h16u;
            float4 b4 = ((const float4*)bias)[lane];
            float sreg[4] = {0.f, 0.f, 0.f, 0.f};
            float qreg[4] = {0.f, 0.f, 0.f, 0.f};
            int gw = b * NWARP + wid;

            for (int d = gw; d < NN; d += TOTW) {
                float sd = g_dis[d];
                float ws = sd * sd;
                uint2 u = Hv[(size_t)d * 32 + lane];
                float2 f0 = __half22float2(*(__half2*)&u.x);
                float2 f1 = __half22float2(*(__half2*)&u.y);
                float4 acc = make_float4(f0.x * ws, f0.y * ws, f1.x * ws, f1.y * ws);

                int beg = g_ptr[d], end = g_ptr[d + 1];
                int j = beg;
                for (; j + 4 <= end; j += 4) {
                    uint2 e0 = g_csr[j + 0], e1 = g_csr[j + 1];
                    uint2 e2 = g_csr[j + 2], e3 = g_csr[j + 3];
                    float w0 = __uint_as_float(e0.y), w1 = __uint_as_float(e1.y);
                    float w2 = __uint_as_float(e2.y), w3 = __uint_as_float(e3.y);
                    uint2 u0 = Hv[(size_t)e0.x * 32 + lane];
                    uint2 u1 = Hv[(size_t)e1.x * 32 + lane];
                    uint2 u2 = Hv[(size_t)e2.x * 32 + lane];
                    uint2 u3 = Hv[(size_t)e3.x * 32 + lane];
                    float2 a0, c0;
                    a0 = __half22float2(*(__half2*)&u0.x);
                    c0 = __half22float2(*(__half2*)&u0.y);
                    acc.x += a0.x * w0; acc.y += a0.y * w0;
                    acc.z += c0.x * w0; acc.w += c0.y * w0;
                    a0 = __half22float2(*(__half2*)&u1.x);
                    c0 = __half22float2(*(__half2*)&u1.y);
                    acc.x += a0.x * w1; acc.y += a0.y * w1;
                    acc.z += c0.x * w1; acc.w += c0.y * w1;
                    a0 = __half22float2(*(__half2*)&u2.x);
                    c0 = __half22float2(*(__half2*)&u2.y);
                    acc.x += a0.x * w2; acc.y += a0.y * w2;
                    acc.z += c0.x * w2; acc.w += c0.y * w2;
                    a0 = __half22float2(*(__half2*)&u3.x);
                    c0 = __half22float2(*(__half2*)&u3.y);
                    acc.x += a0.x * w3; acc.y += a0.y * w3;
                    acc.z += c0.x * w3; acc.w += c0.y * w3;
                }
                for (; j < end; j++) {
                    uint2 e = g_csr[j];
                    float wj = __uint_as_float(e.y);
                    uint2 us = Hv[(size_t)e.x * 32 + lane];
                    float2 a0 = __half22float2(*(__half2*)&us.x);
                    float2 c0 = __half22float2(*(__half2*)&us.y);
                    acc.x += a0.x * wj; acc.y += a0.y * wj;
                    acc.z += c0.x * wj; acc.w += c0.y * wj;
                }
                acc.x += b4.x; acc.y += b4.y; acc.z += b4.z; acc.w += b4.w;
                ((float4*)(g_agg + (size_t)d * HH))[lane] = acc;
                sreg[0] += acc.x; sreg[1] += acc.y;
                sreg[2] += acc.z; sreg[3] += acc.w;
                qreg[0] += acc.x * acc.x; qreg[1] += acc.y * acc.y;
                qreg[2] += acc.z * acc.z; qreg[3] += acc.w * acc.w;
            }
            __syncthreads();  // smem free from gemm phase
            int c0 = 4 * lane;
#pragma unroll
            for (int j = 0; j < 4; j++) {
                ps[wid * HH + c0 + j] = sreg[j];
                pq[wid * HH + c0 + j] = qreg[j];
            }
            __syncthreads();
            if (t < HH) {
                float s = 0.f;
#pragma unroll
                for (int i = 0; i < NWARP; i++) s += ps[i * HH + t];
                g_psC[b * HH + t] = s;
            } else if (t < 2 * HH) {
                int c = t - HH;
                float s = 0.f;
#pragma unroll
                for (int i = 0; i < NWARP; i++) s += pq[i * HH + c];
                g_pqC[b * HH + c] = s;
            }
        }
        gbar(&ep);  // after agg

        // ===== STATS phase (block 0) =====
        if (b == 0 && t < HH) {
            float su = 0.f, q = 0.f;
            for (int cta = 0; cta < BLK; cta++) {
                su += g_psC[cta * HH + t];
                q += g_pqC[cta * HH + t];
            }
            float m = su / (float)NN;
            float var = q / (float)NN - m * m;
            float a = gam[t] * rsqrtf(var + EPSBN);
            g_bn_a[t] = a;
            g_bn_b[t] = bet[t] - m * a;
        }
        gbar(&ep);  // after stats
    }

    // ---------- pool (BN3+ReLU fused) + FC1 ----------
    {
        float* pooled = smem;
        for (int gI = b; gI < GG; gI += BLK) {
            __syncthreads();
            if (t < HH) {
                int beg = g_goff[gI], end = g_goff[gI + 1];
                float a = g_bn_a[t], bb = g_bn_b[t];
                float acc = 0.f;
                for (int r = beg; r < end; r++) {
                    float v = g_agg[(size_t)r * HH + t];
                    acc += fmaxf(a * v + bb, 0.f);
                }
                float cnt = (float)(end - beg);
                pooled[t] = acc / fmaxf(cnt, 1.f);
            }
            __syncthreads();
            if (t < FC1) {
                float s = fcb1[t];
#pragma unroll 8
                for (int k = 0; k < HH; k++) s += pooled[k] * fcW1[k * FC1 + t];
                g_z[gI * FC1 + t] = s;
            }
        }
    }
    gbar(&ep);  // after poolfc1

    // ---------- head (block 0) ----------
    if (b == 0) {
        float* fa = smem;
        float* fb = smem + FC1;
        if (t < FC1) {
            float s = 0.f, q = 0.f;
#pragma unroll 4
            for (int r = 0; r < GG; r++) {
                float v = g_z[r * FC1 + t];
                s += v;
                q += v * v;
            }
            float m = s / (float)GG;
            float var = q / (float)GG - m * m;
            float a = fcg1[t] * rsqrtf(var + EPSBN);
            fa[t] = a;
            fb[t] = fcbe1[t] - m * a;
        }
        __syncthreads();
        if (t < GG) {
            float s = fcb2[0];
#pragma unroll 8
            for (int c = 0; c < FC1; c++) {
                float v = g_z[t * FC1 + c];
                v = fmaxf(fa[c] * v + fb[c], 0.f);
                s += v * fcW2[c];
            }
            out[t] = s;
        }
    }
}

// ---------------- launch ----------------
extern "C" void kernel_launch(void* const* d_in, const int* in_sizes, int n_in,
                              void* d_out, int out_size) {
    const float* x    = (const float*)d_in[0];
    const void*  eidx = d_in[1];
    const void*  batc = d_in[2];

    static int smem_set = 0;
    if (!smem_set) {
        cudaFuncSetAttribute(k_mega, cudaFuncAttributeMaxDynamicSharedMemorySize,
                             GEMM_SMEM);
        smem_set = 1;
    }

    k_reset<<<1, 1>>>();
    k_mega<<<BLK, THR, GEMM_SMEM>>>(
        x, eidx, batc,
        (const float*)d_in[3], (const float*)d_in[4], (const float*)d_in[5],
        (const float*)d_in[6], (const float*)d_in[7], (const float*)d_in[8],
        (const float*)d_in[9], (const float*)d_in[10], (const float*)d_in[11],
        (const float*)d_in[12], (const float*)d_in[13], (const float*)d_in[14],
        (const float*)d_in[15], (const float*)d_in[16], (const float*)d_in[17],
        (const float*)d_in[18], (const float*)d_in[19], (const float*)d_in[20],
        (float*)d_out);
}

// round 8
// speedup vs baseline: 1.2638x; 1.2638x over previous
#include <cuda_runtime.h>
#include <cuda_fp16.h>

#define NN 50000
#define EE 800000
#define HH 128
#define GG 500
#define FC1 64
#define EPSBN 1e-5f
#define AGGP_NB 740       /* 5 blocks/SM * 148 */
#define AGG_WSTRIDE (AGGP_NB * 8)
#define SCAN_TB 256
#define SCAN_NB 196       /* 196*256 = 50176 >= NN */

// ---------------- device scratch (static, no allocation) ----------------
__device__ __align__(16) unsigned g_h16u[NN * (HH / 2)];  // fp16 messages
__device__ float g_agg[NN * HH];
__device__ int   g_cnt[NN];
__device__ int   g_fill[NN];
__device__ int   g_ptr[NN + 1];
__device__ float g_dis[NN];
__device__ __align__(16) uint2 g_csr[EE];   // packed (src, w)
__device__ int   g_bsum[SCAN_NB];
__device__ int   g_boff[SCAN_NB];
__device__ float g_ps1[AGGP_NB * HH];
__device__ float g_pq1[AGGP_NB * HH];
__device__ float g_bn_a[HH];
__device__ float g_bn_b[HH];
__device__ int   g_goff[GG + 1];
__device__ float g_z[GG * FC1];
__device__ float g_wh[3][HH * HH];
__device__ float g_wl[3][HH * HH];
__device__ int   g_tick;      // scanall ticket
__device__ int   g_flag;      // scanall release flag
__device__ int   g_tick2[3];  // aggstats tickets (per layer)
__device__ int   g_is64;

// ---------------- helpers ----------------
__device__ __forceinline__ int ld_idx(const void* p, long long i, int is64) {
    return is64 ? (int)(((const long long*)p)[i]) : ((const int*)p)[i];
}

__device__ __forceinline__ unsigned f2tf32(float v) {
    unsigned o;
    asm("cvt.rna.tf32.f32 %0, %1;" : "=r"(o) : "f"(v));
    return o;
}

// ---------------- pre1: zero + counters + dtype detect + W presplit --------
__global__ void k_pre1(const void* eidx, const float* W1, const float* W2,
                       const float* W3) {
    int i = blockIdx.x * blockDim.x + threadIdx.x;
    if (i < NN) { g_cnt[i] = 0; g_fill[i] = 0; }
    if (i == 0) {
        g_tick = 0; g_flag = 0;
        g_tick2[0] = 0; g_tick2[1] = 0; g_tick2[2] = 0;
    }
    if (blockIdx.x == 0) {
        __shared__ int any;
        if (threadIdx.x == 0) any = 0;
        __syncthreads();
        if (((const int*)eidx)[2 * threadIdx.x + 1] != 0) atomicOr(&any, 1);
        __syncthreads();
        if (threadIdx.x == 0) g_is64 = any ? 0 : 1;
    }
    // W tf32 hi/lo presplit: 3 * 16384 elements
    if (i < 3 * HH * HH) {
        int k = i / (HH * HH);
        int j = i - k * (HH * HH);
        float w = (k == 0) ? W1[j] : (k == 1) ? W2[j] : W3[j];
        unsigned hi = f2tf32(w);
        g_wh[k][j] = __uint_as_float(hi);
        g_wl[k][j] = __uint_as_float(f2tf32(w - __uint_as_float(hi)));
    }
}

// ---------------- count (edge histogram) + graph bounds ----------------
__global__ void k_count(const void* eidx, const void* batch) {
    int e = blockIdx.x * blockDim.x + threadIdx.x;
    int is64 = g_is64;
    if (e < EE) {
        int d = ld_idx(eidx, (long long)EE + e, is64);
        atomicAdd(&g_cnt[d], 1);
    }
    if (e < NN) {
        int b = ld_idx(batch, e, is64);
        int bn = (e + 1 < NN) ? ld_idx(batch, e + 1, is64) : GG;
        if (e == 0)
            for (int g = 0; g <= b && g <= GG; g++) g_goff[g] = 0;
        int hi = bn < GG ? bn : GG;
        for (int g = b + 1; g <= hi; g++) g_goff[g] = e + 1;
    }
}

// ---------------- single-launch CSR scan (ticket + flag spin) ----------------
__global__ void __launch_bounds__(SCAN_TB) k_scanall() {
    __shared__ int sm[SCAN_TB];
    __shared__ int islast;
    int t = threadIdx.x;
    int b = blockIdx.x;
    int i = b * SCAN_TB + t;
    int c = (i < NN) ? g_cnt[i] : 0;
    sm[t] = c;
    __syncthreads();
    for (int off = 1; off < SCAN_TB; off <<= 1) {
        int v = (t >= off) ? sm[t - off] : 0;
        __syncthreads();
        sm[t] += v;
        __syncthreads();
    }
    int local_ex = sm[t] - c;
    int total = sm[SCAN_TB - 1];
    if (t == 0) {
        g_bsum[b] = total;
        __threadfence();
        islast = (atomicAdd(&g_tick, 1) == SCAN_NB - 1);
    }
    __syncthreads();
    if (islast) {
        int v = (t < SCAN_NB) ? g_bsum[t] : 0;
        __syncthreads();
        sm[t] = v;
        __syncthreads();
        for (int off = 1; off < SCAN_TB; off <<= 1) {
            int u = (t >= off) ? sm[t - off] : 0;
            __syncthreads();
            sm[t] += u;
            __syncthreads();
        }
        if (t < SCAN_NB) g_boff[t] = sm[t] - v;
        __threadfence();
        __syncthreads();
        if (t == 0) atomicExch(&g_flag, 1);
    }
    if (t == 0) {
        while (atomicAdd(&g_flag, 0) == 0) __nanosleep(100);
    }
    __syncthreads();
    __threadfence();
    int ex = local_ex + g_boff[b];
    if (i < NN) {
        g_ptr[i] = ex;
        g_dis[i] = rsqrtf((float)(c + 1));
        if (i == NN - 1) g_ptr[NN] = ex + c;
    }
}

__global__ void k_fill(const void* eidx) {
    int e = blockIdx.x * blockDim.x + threadIdx.x;
    if (e >= EE) return;
    int is64 = g_is64;
    int s = ld_idx(eidx, e, is64);
    int d = ld_idx(eidx, (long long)EE + e, is64);
    int pos = atomicAdd(&g_fill[d], 1);
    float w = g_dis[s] * g_dis[d];
    g_csr[g_ptr[d] + pos] = make_uint2((unsigned)s, __float_as_uint(w));
}

// ---------------- 3xTF32 GEMM, W pre-split, 128x128 tile, 512 thr ----------
#define XS_STRIDE 132
#define WS_STRIDE 136
#define GEMM_SMEM ((128 * XS_STRIDE + 2 * 128 * WS_STRIDE) * 4)

template <bool BN>
__global__ void __launch_bounds__(512) k_gemm_tc(const float* __restrict__ X,
                                                 const float* __restrict__ Wh,
                                                 const float* __restrict__ Wl) {
    extern __shared__ float smem[];
    float* Xs  = smem;
    float* Whs = Xs + 128 * XS_STRIDE;
    float* Wls = Whs + 128 * WS_STRIDE;
    int tid = threadIdx.x;
    int row0 = blockIdx.x * 128;

#pragma unroll
    for (int i = 0; i < 8; i++) {
        int q = i * 512 + tid;
        int r = q >> 5;
        int c = (q & 31) * 4;
        int gr = row0 + r;
        float4 v = make_float4(0.f, 0.f, 0.f, 0.f);
        if (gr < NN) v = *(const float4*)(X + (size_t)gr * 128 + c);
        if (BN) {
            v.x = fmaxf(g_bn_a[c + 0] * v.x + g_bn_b[c + 0], 0.f);
            v.y = fmaxf(g_bn_a[c + 1] * v.y + g_bn_b[c + 1], 0.f);
            v.z = fmaxf(g_bn_a[c + 2] * v.z + g_bn_b[c + 2], 0.f);
            v.w = fmaxf(g_bn_a[c + 3] * v.w + g_bn_b[c + 3], 0.f);
        }
        *(float4*)(Xs + r * XS_STRIDE + c) = v;
    }
#pragma unroll
    for (int i = 0; i < 8; i++) {
        int q = i * 512 + tid;
        int r = q >> 5;
        int c = (q & 31) * 4;
        *(float4*)(Whs + r * WS_STRIDE + c) = *(const float4*)(Wh + (size_t)r * 128 + c);
        *(float4*)(Wls + r * WS_STRIDE + c) = *(const float4*)(Wl + (size_t)r * 128 + c);
    }
    __syncthreads();

    int wid = tid >> 5;
    int lane = tid & 31;
    int mwid = wid >> 2;
    int nwid = wid & 3;
    int g = lane >> 2;
    int tg = lane & 3;

    float acc[2][4][4];
#pragma unroll
    for (int mi = 0; mi < 2; mi++)
#pragma unroll
        for (int ni = 0; ni < 4; ni++)
#pragma unroll
            for (int j = 0; j < 4; j++) acc[mi][ni][j] = 0.f;

#define SPLIT(V, HI, LO)                        \
    do {                                        \
        HI = f2tf32(V);                         \
        LO = f2tf32((V) - __uint_as_float(HI)); \
    } while (0)
#define MMA(A0, A1, A2, A3, B0, B1, C)                                  \
    asm volatile(                                                       \
        "mma.sync.aligned.m16n8k8.row.col.f32.tf32.tf32.f32 "           \
        "{%0,%1,%2,%3}, {%4,%5,%6,%7}, {%8,%9}, {%0,%1,%2,%3};"         \
        : "+f"(C[0]), "+f"(C[1]), "+f"(C[2]), "+f"(C[3])                \
        : "r"(A0), "r"(A1), "r"(A2), "r"(A3), "r"(B0), "r"(B1))

#pragma unroll
    for (int k0 = 0; k0 < 128; k0 += 8) {
        unsigned ah[2][4], al[2][4];
#pragma unroll
        for (int mi = 0; mi < 2; mi++) {
            int rb = mwid * 32 + mi * 16;
            int o0 = (rb + g) * XS_STRIDE + k0 + tg;
            int o1 = (rb + g + 8) * XS_STRIDE + k0 + tg;
            float v0 = Xs[o0], v1 = Xs[o1];
            float v2 = Xs[o0 + 4], v3 = Xs[o1 + 4];
            SPLIT(v0, ah[mi][0], al[mi][0]);
            SPLIT(v1, ah[mi][1], al[mi][1]);
            SPLIT(v2, ah[mi][2], al[mi][2]);
            SPLIT(v3, ah[mi][3], al[mi][3]);
        }
        unsigned bh[4][2], bl[4][2];
#pragma unroll
        for (int ni = 0; ni < 4; ni++) {
            int cb = nwid * 32 + ni * 8;
            int o0 = (k0 + tg) * WS_STRIDE + cb + g;
            int o1 = (k0 + tg + 4) * WS_STRIDE + cb + g;
            bh[ni][0] = __float_as_uint(Whs[o0]);
            bh[ni][1] = __float_as_uint(Whs[o1]);
            bl[ni][0] = __float_as_uint(Wls[o0]);
            bl[ni][1] = __float_as_uint(Wls[o1]);
        }
#pragma unroll
        for (int mi = 0; mi < 2; mi++)
#pragma unroll
            for (int ni = 0; ni < 4; ni++) {
                MMA(ah[mi][0], ah[mi][1], ah[mi][2], ah[mi][3],
                    bh[ni][0], bh[ni][1], acc[mi][ni]);
                MMA(ah[mi][0], ah[mi][1], ah[mi][2], ah[mi][3],
                    bl[ni][0], bl[ni][1], acc[mi][ni]);
                MMA(al[mi][0], al[mi][1], al[mi][2], al[mi][3],
                    bh[ni][0], bh[ni][1], acc[mi][ni]);
            }
    }
#undef MMA
#undef SPLIT

#pragma unroll
    for (int mi = 0; mi < 2; mi++) {
#pragma unroll
        for (int ni = 0; ni < 4; ni++) {
            int col = nwid * 32 + ni * 8 + tg * 2;
            int r1 = row0 + mwid * 32 + mi * 16 + g;
            int r2 = r1 + 8;
            if (r1 < NN) {
                __half2 h = __floats2half2_rn(acc[mi][ni][0], acc[mi][ni][1]);
                g_h16u[(size_t)r1 * 64 + (col >> 1)] = *(unsigned*)&h;
            }
            if (r2 < NN) {
                __half2 h = __floats2half2_rn(acc[mi][ni][2], acc[mi][ni][3]);
                g_h16u[(size_t)r2 * 64 + (col >> 1)] = *(unsigned*)&h;
            }
        }
    }
}

// ------- aggregation (fp16 gather) + per-block stats + ticketed finalize ----
// Grid AGGP_NB=740 blocks x 256 thr (5/SM, full occupancy). Each warp strides
// nodes; block partials -> g_ps1/g_pq1[block]; last-finishing block reduces
// 740 partial rows and writes bn_a/bn_b (deterministic fixed-order sums).
__global__ void __launch_bounds__(256) k_aggstats(const float* __restrict__ bias,
                                                  const float* __restrict__ gam,
                                                  const float* __restrict__ bet,
                                                  int which) {
    __shared__ float ps[8][HH];
    __shared__ float pq[8][HH];
    __shared__ int islast;
    int w = threadIdx.x >> 5;
    int lane = threadIdx.x & 31;
    int b = blockIdx.x;
    int t = threadIdx.x;

    const uint2* Hv = (const uint2*)g_h16u;
    float4 b4 = ((const float4*)bias)[lane];
    float sreg[4] = {0.f, 0.f, 0.f, 0.f};
    float qreg[4] = {0.f, 0.f, 0.f, 0.f};

    for (int d = b * 8 + w; d < NN; d += AGG_WSTRIDE) {
        float sd = g_dis[d];
        float ws = sd * sd;
        uint2 u = Hv[(size_t)d * 32 + lane];
        float2 f0 = __half22float2(*(__half2*)&u.x);
        float2 f1 = __half22float2(*(__half2*)&u.y);
        float4 acc = make_float4(f0.x * ws, f0.y * ws, f1.x * ws, f1.y * ws);

        int beg = g_ptr[d], end = g_ptr[d + 1];
        int j = beg;
        for (; j + 4 <= end; j += 4) {
            uint2 e0 = g_csr[j + 0], e1 = g_csr[j + 1];
            uint2 e2 = g_csr[j + 2], e3 = g_csr[j + 3];
            float w0 = __uint_as_float(e0.y), w1 = __uint_as_float(e1.y);
            float w2 = __uint_as_float(e2.y), w3 = __uint_as_float(e3.y);
            uint2 u0 = Hv[(size_t)e0.x * 32 + lane];
            uint2 u1 = Hv[(size_t)e1.x * 32 + lane];
            uint2 u2 = Hv[(size_t)e2.x * 32 + lane];
            uint2 u3 = Hv[(size_t)e3.x * 32 + lane];
            float2 a0, c0;
            a0 = __half22float2(*(__half2*)&u0.x);
            c0 = __half22float2(*(__half2*)&u0.y);
            acc.x += a0.x * w0; acc.y += a0.y * w0;
            acc.z += c0.x * w0; acc.w += c0.y * w0;
            a0 = __half22float2(*(__half2*)&u1.x);
            c0 = __half22float2(*(__half2*)&u1.y);
            acc.x += a0.x * w1; acc.y += a0.y * w1;
            acc.z += c0.x * w1; acc.w += c0.y * w1;
            a0 = __half22float2(*(__half2*)&u2.x);
            c0 = __half22float2(*(__half2*)&u2.y);
            acc.x += a0.x * w2; acc.y += a0.y * w2;
            acc.z += c0.x * w2; acc.w += c0.y * w2;
            a0 = __half22float2(*(__half2*)&u3.x);
            c0 = __half22float2(*(__half2*)&u3.y);
            acc.x += a0.x * w3; acc.y += a0.y * w3;
            acc.z += c0.x * w3; acc.w += c0.y * w3;
        }
        for (; j < end; j++) {
            uint2 e = g_csr[j];
            float wj = __uint_as_float(e.y);
            uint2 us = Hv[(size_t)e.x * 32 + lane];
            float2 a0 = __half22float2(*(__half2*)&us.x);
            float2 c0 = __half22float2(*(__half2*)&us.y);
            acc.x += a0.x * wj; acc.y += a0.y * wj;
            acc.z += c0.x * wj; acc.w += c0.y * wj;
        }
        acc.x += b4.x; acc.y += b4.y; acc.z += b4.z; acc.w += b4.w;
        ((float4*)(g_agg + (size_t)d * HH))[lane] = acc;
        sreg[0] += acc.x; sreg[1] += acc.y;
        sreg[2] += acc.z; sreg[3] += acc.w;
        qreg[0] += acc.x * acc.x; qreg[1] += acc.y * acc.y;
        qreg[2] += acc.z * acc.z; qreg[3] += acc.w * acc.w;
    }

    int c0i = 4 * lane;
#pragma unroll
    for (int j = 0; j < 4; j++) {
        ps[w][c0i + j] = sreg[j];
        pq[w][c0i + j] = qreg[j];
    }
    __syncthreads();
    if (t < HH) {
        float s = 0.f;
#pragma unroll
        for (int i = 0; i < 8; i++) s += ps[i][t];
        g_ps1[b * HH + t] = s;
    } else {
        int c = t - HH;
        float s = 0.f;
#pragma unroll
        for (int i = 0; i < 8; i++) s += pq[i][c];
        g_pq1[b * HH + c] = s;
    }
    __threadfence();
    __syncthreads();
    if (t == 0) islast = (atomicAdd(&g_tick2[which], 1) == AGGP_NB - 1);
    __syncthreads();
    if (!islast) return;
    __threadfence();
    if (t < HH) {
        float su = 0.f, q = 0.f;
        for (int i = 0; i < AGGP_NB; i++) {
            su += g_ps1[i * HH + t];
            q += g_pq1[i * HH + t];
        }
        float m = su / (float)NN;
        float var = q / (float)NN - m * m;
        float a = gam[t] * rsqrtf(var + EPSBN);
        g_bn_a[t] = a;
        g_bn_b[t] = bet[t] - m * a;
    }
}

// ---------------- pool (BN3+ReLU fused) + FC1, one kernel ----------------
__global__ void __launch_bounds__(128) k_poolfc1(const float* __restrict__ Wf,
                                                 const float* __restrict__ bf) {
    __shared__ float pooled[HH];
    int gI = blockIdx.x;
    int c = threadIdx.x;
    int beg = g_goff[gI], end = g_goff[gI + 1];
    float a = g_bn_a[c], b = g_bn_b[c];
    float acc = 0.f;
    for (int r = beg; r < end; r++) {
        float v = g_agg[(size_t)r * HH + c];
        acc += fmaxf(a * v + b, 0.f);
    }
    float cnt = (float)(end - beg);
    pooled[c] = acc / fmaxf(cnt, 1.f);
    __syncthreads();
    if (c < FC1) {
        float s = bf[c];
#pragma unroll 8
        for (int k = 0; k < HH; k++) s += pooled[k] * Wf[k * FC1 + c];
        g_z[gI * FC1 + c] = s;
    }
}

// ---------------- head: fc BN stats + fc2, one block ----------------
__global__ void __launch_bounds__(512) k_head(const float* __restrict__ gam,
                                              const float* __restrict__ bet,
                                              const float* __restrict__ W2f,
                                              const float* __restrict__ b2f,
                                              float* __restrict__ out) {
    __shared__ float fa[FC1], fb[FC1];
    int t = threadIdx.x;
    if (t < FC1) {
        float s = 0.f, q = 0.f;
#pragma unroll 4
        for (int r = 0; r < GG; r++) {
            float v = g_z[r * FC1 + t];
            s += v;
            q += v * v;
        }
        float m = s / (float)GG;
        float var = q / (float)GG - m * m;
        float a = gam[t] * rsqrtf(var + EPSBN);
        fa[t] = a;
        fb[t] = bet[t] - m * a;
    }
    __syncthreads();
    if (t < GG) {
        float s = b2f[0];
#pragma unroll 8
        for (int c = 0; c < FC1; c++) {
            float v = g_z[t * FC1 + c];
            v = fmaxf(fa[c] * v + fb[c], 0.f);
            s += v * W2f[c];
        }
        out[t] = s;
    }
}

// ---------------- launch ----------------
extern "C" void kernel_launch(void* const* d_in, const int* in_sizes, int n_in,
                              void* d_out, int out_size) {
    const float* x    = (const float*)d_in[0];
    const void*  eidx = d_in[1];
    const void*  batc = d_in[2];
    const float* W1 = (const float*)d_in[3];
    const float* b1 = (const float*)d_in[4];
    const float* g1 = (const float*)d_in[5];
    const float* be1 = (const float*)d_in[6];
    const float* W2 = (const float*)d_in[7];
    const float* b2 = (const float*)d_in[8];
    const float* g2 = (const float*)d_in[9];
    const float* be2 = (const float*)d_in[10];
    const float* W3 = (const float*)d_in[11];
    const float* b3 = (const float*)d_in[12];
    const float* g3 = (const float*)d_in[13];
    const float* be3 = (const float*)d_in[14];
    const float* fcW1 = (const float*)d_in[15];
    const float* fcb1 = (const float*)d_in[16];
    const float* fcg1 = (const float*)d_in[17];
    const float* fcbe1 = (const float*)d_in[18];
    const float* fcW2 = (const float*)d_in[19];
    const float* fcb2 = (const float*)d_in[20];
    float* out = (float*)d_out;

    float *pagg = nullptr, *pwh = nullptr, *pwl = nullptr;
    cudaGetSymbolAddress((void**)&pagg, g_agg);
    cudaGetSymbolAddress((void**)&pwh, g_wh);
    cudaGetSymbolAddress((void**)&pwl, g_wl);

    const int TB = 256;
    const int gemm_blocks = (NN + 127) / 128;

    static int init_done = 0;
    static cudaStream_t s2;
    static cudaEvent_t ev1, ev2;
    if (!init_done) {
        cudaFuncSetAttribute(k_gemm_tc<false>,
                             cudaFuncAttributeMaxDynamicSharedMemorySize, GEMM_SMEM);
        cudaFuncSetAttribute(k_gemm_tc<true>,
                             cudaFuncAttributeMaxDynamicSharedMemorySize, GEMM_SMEM);
        cudaStreamCreateWithFlags(&s2, cudaStreamNonBlocking);
        cudaEventCreateWithFlags(&ev1, cudaEventDisableTiming);
        cudaEventCreateWithFlags(&ev2, cudaEventDisableTiming);
        init_done = 1;
    }

    // preprocessing chain on main stream; layer-1 GEMM forked onto s2
    k_pre1<<<SCAN_NB, TB>>>(eidx, W1, W2, W3);
    cudaEventRecord(ev1, 0);
    cudaStreamWaitEvent(s2, ev1, 0);
    k_gemm_tc<false><<<gemm_blocks, 512, GEMM_SMEM, s2>>>(x, pwh, pwl);
    cudaEventRecord(ev2, s2);

    k_count<<<(EE + TB - 1) / TB, TB>>>(eidx, batc);
    k_scanall<<<SCAN_NB, SCAN_TB>>>();
    k_fill<<<(EE + TB - 1) / TB, TB>>>(eidx);
    cudaStreamWaitEvent(0, ev2, 0);

    // layer 1
    k_aggstats<<<AGGP_NB, TB>>>(b1, g1, be1, 0);
    // layer 2
    k_gemm_tc<true><<<gemm_blocks, 512, GEMM_SMEM>>>(pagg, pwh + HH * HH, pwl + HH * HH);
    k_aggstats<<<AGGP_NB, TB>>>(b2, g2, be2, 1);
    // layer 3
    k_gemm_tc<true><<<gemm_blocks, 512, GEMM_SMEM>>>(pagg, pwh + 2 * HH * HH, pwl + 2 * HH * HH);
    k_aggstats<<<AGGP_NB, TB>>>(b3, g3, be3, 2);

    // pool+fc1, then head
    k_poolfc1<<<GG, 128>>>(fcW1, fcb1);
    k_head<<<1, 512>>>(fcg1, fcbe1, fcW2, fcb2, out);
}

// round 9
// speedup vs baseline: 1.3553x; 1.0724x over previous
#include <cuda_runtime.h>
#include <cuda_fp16.h>

#define NN 50000
#define EE 800000
#define HH 128
#define GG 500
#define FC1 64
#define EPSBN 1e-5f
#define AGG_NB 6250      /* 50000/8 */
#define STAT_NB 128
#define SCAN_TB 256
#define SCAN_NB 196      /* 196*256 = 50176 >= NN */

// ---------------- device scratch (static, no allocation) ----------------
__device__ __align__(16) unsigned g_h16u[NN * (HH / 2)];  // fp16 messages
__device__ float g_agg[NN * HH];
__device__ int   g_cnt[NN];
__device__ int   g_fill[NN];
__device__ int   g_ptr[NN + 1];
__device__ float g_dis[NN];
__device__ __align__(16) uint2 g_csr[EE];   // packed (src, w)
__device__ int   g_bsum[SCAN_NB];
__device__ int   g_boff[SCAN_NB];
__device__ float g_ps1[AGG_NB * HH];
__device__ float g_pq1[AGG_NB * HH];
__device__ float g_mids[STAT_NB * HH];
__device__ float g_midq[STAT_NB * HH];
__device__ float g_bn_a[HH];
__device__ float g_bn_b[HH];
__device__ int   g_goff[GG + 1];
__device__ float g_z[GG * FC1];
__device__ float g_wh[3][HH * HH];
__device__ float g_wl[3][HH * HH];
__device__ int   g_tick;      // scanall ticket
__device__ int   g_flag;      // scanall release flag
__device__ int   g_tick2[3];  // stats tickets (per layer)
__device__ int   g_is64;

// ---------------- helpers ----------------
__device__ __forceinline__ int ld_idx(const void* p, long long i, int is64) {
    return is64 ? (int)(((const long long*)p)[i]) : ((const int*)p)[i];
}

__device__ __forceinline__ unsigned f2tf32(float v) {
    unsigned o;
    asm("cvt.rna.tf32.f32 %0, %1;" : "=r"(o) : "f"(v));
    return o;
}

// ---------------- pre1: zero + counters + dtype detect + W presplit --------
__global__ void k_pre1(const void* eidx, const float* W1, const float* W2,
                       const float* W3) {
    int i = blockIdx.x * blockDim.x + threadIdx.x;
    if (i < NN) { g_cnt[i] = 0; g_fill[i] = 0; }
    if (i == 0) {
        g_tick = 0; g_flag = 0;
        g_tick2[0] = 0; g_tick2[1] = 0; g_tick2[2] = 0;
    }
    if (blockIdx.x == 0) {
        __shared__ int any;
        if (threadIdx.x == 0) any = 0;
        __syncthreads();
        if (((const int*)eidx)[2 * threadIdx.x + 1] != 0) atomicOr(&any, 1);
        __syncthreads();
        if (threadIdx.x == 0) g_is64 = any ? 0 : 1;
    }
    if (i < 3 * HH * HH) {
        int k = i / (HH * HH);
        int j = i - k * (HH * HH);
        float w = (k == 0) ? W1[j] : (k == 1) ? W2[j] : W3[j];
        unsigned hi = f2tf32(w);
        g_wh[k][j] = __uint_as_float(hi);
        g_wl[k][j] = __uint_as_float(f2tf32(w - __uint_as_float(hi)));
    }
}

// ---------------- count (edge histogram) + graph bounds ----------------
__global__ void k_count(const void* eidx, const void* batch) {
    int e = blockIdx.x * blockDim.x + threadIdx.x;
    int is64 = g_is64;
    if (e < EE) {
        int d = ld_idx(eidx, (long long)EE + e, is64);
        atomicAdd(&g_cnt[d], 1);
    }
    if (e < NN) {
        int b = ld_idx(batch, e, is64);
        int bn = (e + 1 < NN) ? ld_idx(batch, e + 1, is64) : GG;
        if (e == 0)
            for (int g = 0; g <= b && g <= GG; g++) g_goff[g] = 0;
        int hi = bn < GG ? bn : GG;
        for (int g = b + 1; g <= hi; g++) g_goff[g] = e + 1;
    }
}

// ---------------- single-launch CSR scan (ticket + flag spin) ----------------
__global__ void __launch_bounds__(SCAN_TB) k_scanall() {
    __shared__ int sm[SCAN_TB];
    __shared__ int islast;
    int t = threadIdx.x;
    int b = blockIdx.x;
    int i = b * SCAN_TB + t;
    int c = (i < NN) ? g_cnt[i] : 0;
    sm[t] = c;
    __syncthreads();
    for (int off = 1; off < SCAN_TB; off <<= 1) {
        int v = (t >= off) ? sm[t - off] : 0;
        __syncthreads();
        sm[t] += v;
        __syncthreads();
    }
    int local_ex = sm[t] - c;
    int total = sm[SCAN_TB - 1];
    if (t == 0) {
        g_bsum[b] = total;
        __threadfence();
        islast = (atomicAdd(&g_tick, 1) == SCAN_NB - 1);
    }
    __syncthreads();
    if (islast) {
        int v = (t < SCAN_NB) ? g_bsum[t] : 0;
        __syncthreads();
        sm[t] = v;
        __syncthreads();
        for (int off = 1; off < SCAN_TB; off <<= 1) {
            int u = (t >= off) ? sm[t - off] : 0;
            __syncthreads();
            sm[t] += u;
            __syncthreads();
        }
        if (t < SCAN_NB) g_boff[t] = sm[t] - v;
        __threadfence();
        __syncthreads();
        if (t == 0) atomicExch(&g_flag, 1);
    }
    if (t == 0) {
        while (atomicAdd(&g_flag, 0) == 0) __nanosleep(100);
    }
    __syncthreads();
    __threadfence();
    int ex = local_ex + g_boff[b];
    if (i < NN) {
        g_ptr[i] = ex;
        g_dis[i] = rsqrtf((float)(c + 1));
        if (i == NN - 1) g_ptr[NN] = ex + c;
    }
}

__global__ void k_fill(const void* eidx) {
    int e = blockIdx.x * blockDim.x + threadIdx.x;
    if (e >= EE) return;
    int is64 = g_is64;
    int s = ld_idx(eidx, e, is64);
    int d = ld_idx(eidx, (long long)EE + e, is64);
    int pos = atomicAdd(&g_fill[d], 1);
    float w = g_dis[s] * g_dis[d];
    g_csr[g_ptr[d] + pos] = make_uint2((unsigned)s, __float_as_uint(w));
}

// ------- 3xTF32 GEMM, K-split (2 chunks of 64) -> 104KB smem, 2 CTAs/SM -----
// g_h16u[N,128](fp16) = f(X)[N,128] @ W[128,128]; f = id or BN+ReLU.
// 512 thr, warps 4(M)x4(N), warp tile 32x32 (2x4 m16n8k8).
#define XS_STRIDE 68
#define WS_STRIDE 136
#define GEMM_SMEM ((128 * XS_STRIDE + 2 * 64 * WS_STRIDE) * 4)

template <bool BN>
__global__ void __launch_bounds__(512, 2) k_gemm_tc(const float* __restrict__ X,
                                                    const float* __restrict__ Wh,
                                                    const float* __restrict__ Wl) {
    extern __shared__ float smem[];
    float* Xs  = smem;                        // [128][68] fp32 chunk
    float* Whs = Xs + 128 * XS_STRIDE;        // [64][136] tf32-hi chunk
    float* Wls = Whs + 64 * WS_STRIDE;        // [64][136] tf32-lo chunk
    int tid = threadIdx.x;
    int row0 = blockIdx.x * 128;

    int wid = tid >> 5;
    int lane = tid & 31;
    int mwid = wid >> 2;
    int nwid = wid & 3;
    int g = lane >> 2;
    int tg = lane & 3;

    float acc[2][4][4];
#pragma unroll
    for (int mi = 0; mi < 2; mi++)
#pragma unroll
        for (int ni = 0; ni < 4; ni++)
#pragma unroll
            for (int j = 0; j < 4; j++) acc[mi][ni][j] = 0.f;

#define SPLIT(V, HI, LO)                        \
    do {                                        \
        HI = f2tf32(V);                         \
        LO = f2tf32((V) - __uint_as_float(HI)); \
    } while (0)
#define MMA(A0, A1, A2, A3, B0, B1, C)                                  \
    asm volatile(                                                       \
        "mma.sync.aligned.m16n8k8.row.col.f32.tf32.tf32.f32 "           \
        "{%0,%1,%2,%3}, {%4,%5,%6,%7}, {%8,%9}, {%0,%1,%2,%3};"         \
        : "+f"(C[0]), "+f"(C[1]), "+f"(C[2]), "+f"(C[3])                \
        : "r"(A0), "r"(A1), "r"(A2), "r"(A3), "r"(B0), "r"(B1))

#pragma unroll
    for (int kc = 0; kc < 2; kc++) {
        int kb = kc * 64;
        __syncthreads();  // previous chunk's reads done before overwrite
        // X chunk 128x64 (fused BN+ReLU): 2048 f4 / 512 thr = 4 each
#pragma unroll
        for (int i = 0; i < 4; i++) {
            int q = i * 512 + tid;
            int r = q >> 4;
            int c = (q & 15) * 4;
            int gr = row0 + r;
            float4 v = make_float4(0.f, 0.f, 0.f, 0.f);
            if (gr < NN) v = *(const float4*)(X + (size_t)gr * 128 + kb + c);
            if (BN) {
                int ch = kb + c;
                v.x = fmaxf(g_bn_a[ch + 0] * v.x + g_bn_b[ch + 0], 0.f);
                v.y = fmaxf(g_bn_a[ch + 1] * v.y + g_bn_b[ch + 1], 0.f);
                v.z = fmaxf(g_bn_a[ch + 2] * v.z + g_bn_b[ch + 2], 0.f);
                v.w = fmaxf(g_bn_a[ch + 3] * v.w + g_bn_b[ch + 3], 0.f);
            }
            *(float4*)(Xs + r * XS_STRIDE + c) = v;
        }
        // W hi/lo chunk rows kb..kb+63 x 128 cols
#pragma unroll
        for (int i = 0; i < 4; i++) {
            int q = i * 512 + tid;
            int r = q >> 5;
            int c = (q & 31) * 4;
            *(float4*)(Whs + r * WS_STRIDE + c) =
                *(const float4*)(Wh + (size_t)(kb + r) * 128 + c);
            *(float4*)(Wls + r * WS_STRIDE + c) =
                *(const float4*)(Wl + (size_t)(kb + r) * 128 + c);
        }
        __syncthreads();

#pragma unroll
        for (int k0 = 0; k0 < 64; k0 += 8) {
            unsigned ah[2][4], al[2][4];
#pragma unroll
            for (int mi = 0; mi < 2; mi++) {
                int rb = mwid * 32 + mi * 16;
                int o0 = (rb + g) * XS_STRIDE + k0 + tg;
                int o1 = (rb + g + 8) * XS_STRIDE + k0 + tg;
                float v0 = Xs[o0], v1 = Xs[o1];
                float v2 = Xs[o0 + 4], v3 = Xs[o1 + 4];
                SPLIT(v0, ah[mi][0], al[mi][0]);
                SPLIT(v1, ah[mi][1], al[mi][1]);
                SPLIT(v2, ah[mi][2], al[mi][2]);
                SPLIT(v3, ah[mi][3], al[mi][3]);
            }
            // b fragments loaded per-ni to keep register pressure under 64
#pragma unroll
            for (int ni = 0; ni < 4; ni++) {
                int cb = nwid * 32 + ni * 8;
                int o0 = (k0 + tg) * WS_STRIDE + cb + g;
                int o1 = (k0 + tg + 4) * WS_STRIDE + cb + g;
                unsigned bh0 = __float_as_uint(Whs[o0]);
                unsigned bh1 = __float_as_uint(Whs[o1]);
                unsigned bl0 = __float_as_uint(Wls[o0]);
                unsigned bl1 = __float_as_uint(Wls[o1]);
#pragma unroll
                for (int mi = 0; mi < 2; mi++) {
                    MMA(ah[mi][0], ah[mi][1], ah[mi][2], ah[mi][3],
                        bh0, bh1, acc[mi][ni]);
                    MMA(ah[mi][0], ah[mi][1], ah[mi][2], ah[mi][3],
                        bl0, bl1, acc[mi][ni]);
                    MMA(al[mi][0], al[mi][1], al[mi][2], al[mi][3],
                        bh0, bh1, acc[mi][ni]);
                }
            }
        }
    }
#undef MMA
#undef SPLIT

    // epilogue: fp16 pairs
#pragma unroll
    for (int mi = 0; mi < 2; mi++) {
#pragma unroll
        for (int ni = 0; ni < 4; ni++) {
            int col = nwid * 32 + ni * 8 + tg * 2;
            int r1 = row0 + mwid * 32 + mi * 16 + g;
            int r2 = r1 + 8;
            if (r1 < NN) {
                __half2 h = __floats2half2_rn(acc[mi][ni][0], acc[mi][ni][1]);
                g_h16u[(size_t)r1 * 64 + (col >> 1)] = *(unsigned*)&h;
            }
            if (r2 < NN) {
                __half2 h = __floats2half2_rn(acc[mi][ni][2], acc[mi][ni][3]);
                g_h16u[(size_t)r2 * 64 + (col >> 1)] = *(unsigned*)&h;
            }
        }
    }
}

// ---------------- aggregation (fp16 gather) + fused BN partial stats --------
__global__ void __launch_bounds__(256) k_agg(const float* __restrict__ bias) {
    __shared__ float ps[8][HH];
    __shared__ float pq[8][HH];
    int w = threadIdx.x >> 5;
    int lane = threadIdx.x & 31;
    int d = blockIdx.x * 8 + w;   // NN = 6250*8 exact

    const uint2* Hv = (const uint2*)g_h16u;
    float sd = g_dis[d];
    float ws = sd * sd;
    uint2 u = Hv[(size_t)d * 32 + lane];
    float2 f0 = __half22float2(*(__half2*)&u.x);
    float2 f1 = __half22float2(*(__half2*)&u.y);
    float4 acc = make_float4(f0.x * ws, f0.y * ws, f1.x * ws, f1.y * ws);

    int beg = g_ptr[d], end = g_ptr[d + 1];
    int j = beg;
    for (; j + 4 <= end; j += 4) {
        uint2 e0 = g_csr[j + 0], e1 = g_csr[j + 1];
        uint2 e2 = g_csr[j + 2], e3 = g_csr[j + 3];
        float w0 = __uint_as_float(e0.y), w1 = __uint_as_float(e1.y);
        float w2 = __uint_as_float(e2.y), w3 = __uint_as_float(e3.y);
        uint2 u0 = Hv[(size_t)e0.x * 32 + lane];
        uint2 u1 = Hv[(size_t)e1.x * 32 + lane];
        uint2 u2 = Hv[(size_t)e2.x * 32 + lane];
        uint2 u3 = Hv[(size_t)e3.x * 32 + lane];
        float2 a0, c0;
        a0 = __half22float2(*(__half2*)&u0.x); c0 = __half22float2(*(__half2*)&u0.y);
        acc.x += a0.x * w0; acc.y += a0.y * w0; acc.z += c0.x * w0; acc.w += c0.y * w0;
        a0 = __half22float2(*(__half2*)&u1.x); c0 = __half22float2(*(__half2*)&u1.y);
        acc.x += a0.x * w1; acc.y += a0.y * w1; acc.z += c0.x * w1; acc.w += c0.y * w1;
        a0 = __half22float2(*(__half2*)&u2.x); c0 = __half22float2(*(__half2*)&u2.y);
        acc.x += a0.x * w2; acc.y += a0.y * w2; acc.z += c0.x * w2; acc.w += c0.y * w2;
        a0 = __half22float2(*(__half2*)&u3.x); c0 = __half22float2(*(__half2*)&u3.y);
        acc.x += a0.x * w3; acc.y += a0.y * w3; acc.z += c0.x * w3; acc.w += c0.y * w3;
    }
    for (; j < end; j++) {
        uint2 e = g_csr[j];
        float wj = __uint_as_float(e.y);
        uint2 us = Hv[(size_t)e.x * 32 + lane];
        float2 a0 = __half22float2(*(__half2*)&us.x);
        float2 c0 = __half22float2(*(__half2*)&us.y);
        acc.x += a0.x * wj; acc.y += a0.y * wj; acc.z += c0.x * wj; acc.w += c0.y * wj;
    }
    float4 b4 = ((const float4*)bias)[lane];
    acc.x += b4.x; acc.y += b4.y; acc.z += b4.z; acc.w += b4.w;
    ((float4*)(g_agg + (size_t)d * HH))[lane] = acc;

    int c0i = 4 * lane;
    ps[w][c0i + 0] = acc.x; ps[w][c0i + 1] = acc.y;
    ps[w][c0i + 2] = acc.z; ps[w][c0i + 3] = acc.w;
    pq[w][c0i + 0] = acc.x * acc.x; pq[w][c0i + 1] = acc.y * acc.y;
    pq[w][c0i + 2] = acc.z * acc.z; pq[w][c0i + 3] = acc.w * acc.w;
    __syncthreads();
    int t = threadIdx.x;
    if (t < HH) {
        float s = 0.f;
#pragma unroll
        for (int i = 0; i < 8; i++) s += ps[i][t];
        g_ps1[blockIdx.x * HH + t] = s;
    } else {
        int c = t - HH;
        float s = 0.f;
#pragma unroll
        for (int i = 0; i < 8; i++) s += pq[i][c];
        g_pq1[blockIdx.x * HH + c] = s;
    }
}

// ---------------- BN stats: one launch (mid + ticketed final) ----------------
#define ROWS_PER_STAT 49  /* 128*49 = 6272 >= 6250 */
__global__ void __launch_bounds__(256) k_stats(int which,
                                               const float* __restrict__ gam,
                                               const float* __restrict__ bet) {
    __shared__ int islast;
    int b = blockIdx.x;
    int t = threadIdx.x;
    int c = t & (HH - 1);
    int isq = t >> 7;
    const float* src = isq ? g_pq1 : g_ps1;
    float s = 0.f;
    int r0 = b * ROWS_PER_STAT;
    int r1 = r0 + ROWS_PER_STAT;
    if (r1 > AGG_NB) r1 = AGG_NB;
    for (int r = r0; r < r1; r++) s += src[r * HH + c];
    if (isq) g_midq[b * HH + c] = s;
    else     g_mids[b * HH + c] = s;
    __threadfence();
    if (t == 0) islast = (atomicAdd(&g_tick2[which], 1) == STAT_NB - 1);
    __syncthreads();
    if (!islast) return;
    if (t < HH) {
        float su = 0.f, q = 0.f;
        for (int b2 = 0; b2 < STAT_NB; b2++) {
            su += g_mids[b2 * HH + t];
            q  += g_midq[b2 * HH + t];
        }
        float m = su / (float)NN;
        float var = q / (float)NN - m * m;
        float a = gam[t] * rsqrtf(var + EPSBN);
        g_bn_a[t] = a;
        g_bn_b[t] = bet[t] - m * a;
    }
}

// ---------------- pool (BN3+ReLU fused) + FC1, one kernel ----------------
__global__ void __launch_bounds__(128) k_poolfc1(const float* __restrict__ Wf,
                                                 const float* __restrict__ bf) {
    __shared__ float pooled[HH];
    int gI = blockIdx.x;
    int c = threadIdx.x;
    int beg = g_goff[gI], end = g_goff[gI + 1];
    float a = g_bn_a[c], b = g_bn_b[c];
    float acc = 0.f;
    for (int r = beg; r < end; r++) {
        float v = g_agg[(size_t)r * HH + c];
        acc += fmaxf(a * v + b, 0.f);
    }
    float cnt = (float)(end - beg);
    pooled[c] = acc / fmaxf(cnt, 1.f);
    __syncthreads();
    if (c < FC1) {
        float s = bf[c];
#pragma unroll 8
        for (int k = 0; k < HH; k++) s += pooled[k] * Wf[k * FC1 + c];
        g_z[gI * FC1 + c] = s;
    }
}

// ---------------- head: fc BN stats + fc2, one block ----------------
__global__ void __launch_bounds__(512) k_head(const float* __restrict__ gam,
                                              const float* __restrict__ bet,
                                              const float* __restrict__ W2f,
                                              const float* __restrict__ b2f,
                                              float* __restrict__ out) {
    __shared__ float fa[FC1], fb[FC1];
    int t = threadIdx.x;
    if (t < FC1) {
        float s = 0.f, q = 0.f;
#pragma unroll 4
        for (int r = 0; r < GG; r++) {
            float v = g_z[r * FC1 + t];
            s += v;
            q += v * v;
        }
        float m = s / (float)GG;
        float var = q / (float)GG - m * m;
        float a = gam[t] * rsqrtf(var + EPSBN);
        fa[t] = a;
        fb[t] = bet[t] - m * a;
    }
    __syncthreads();
    if (t < GG) {
        float s = b2f[0];
#pragma unroll 8
        for (int c = 0; c < FC1; c++) {
            float v = g_z[t * FC1 + c];
            v = fmaxf(fa[c] * v + fb[c], 0.f);
            s += v * W2f[c];
        }
        out[t] = s;
    }
}

// ---------------- launch ----------------
extern "C" void kernel_launch(void* const* d_in, const int* in_sizes, int n_in,
                              void* d_out, int out_size) {
    const float* x    = (const float*)d_in[0];
    const void*  eidx = d_in[1];
    const void*  batc = d_in[2];
    const float* W1 = (const float*)d_in[3];
    const float* b1 = (const float*)d_in[4];
    const float* g1 = (const float*)d_in[5];
    const float* be1 = (const float*)d_in[6];
    const float* W2 = (const float*)d_in[7];
    const float* b2 = (const float*)d_in[8];
    const float* g2 = (const float*)d_in[9];
    const float* be2 = (const float*)d_in[10];
    const float* W3 = (const float*)d_in[11];
    const float* b3 = (const float*)d_in[12];
    const float* g3 = (const float*)d_in[13];
    const float* be3 = (const float*)d_in[14];
    const float* fcW1 = (const float*)d_in[15];
    const float* fcb1 = (const float*)d_in[16];
    const float* fcg1 = (const float*)d_in[17];
    const float* fcbe1 = (const float*)d_in[18];
    const float* fcW2 = (const float*)d_in[19];
    const float* fcb2 = (const float*)d_in[20];
    float* out = (float*)d_out;

    float *pagg = nullptr, *pwh = nullptr, *pwl = nullptr;
    cudaGetSymbolAddress((void**)&pagg, g_agg);
    cudaGetSymbolAddress((void**)&pwh, g_wh);
    cudaGetSymbolAddress((void**)&pwl, g_wl);

    const int TB = 256;
    const int gemm_blocks = (NN + 127) / 128;

    static int init_done = 0;
    if (!init_done) {
        cudaFuncSetAttribute(k_gemm_tc<false>,
                             cudaFuncAttributeMaxDynamicSharedMemorySize, GEMM_SMEM);
        cudaFuncSetAttribute(k_gemm_tc<true>,
                             cudaFuncAttributeMaxDynamicSharedMemorySize, GEMM_SMEM);
        init_done = 1;
    }

    k_pre1<<<SCAN_NB, TB>>>(eidx, W1, W2, W3);
    k_count<<<(EE + TB - 1) / TB, TB>>>(eidx, batc);
    k_scanall<<<SCAN_NB, SCAN_TB>>>();
    k_fill<<<(EE + TB - 1) / TB, TB>>>(eidx);

    // layer 1
    k_gemm_tc<false><<<gemm_blocks, 512, GEMM_SMEM>>>(x, pwh, pwl);
    k_agg<<<AGG_NB, TB>>>(b1);
    k_stats<<<STAT_NB, TB>>>(0, g1, be1);
    // layer 2
    k_gemm_tc<true><<<gemm_blocks, 512, GEMM_SMEM>>>(pagg, pwh + HH * HH, pwl + HH * HH);
    k_agg<<<AGG_NB, TB>>>(b2);
    k_stats<<<STAT_NB, TB>>>(1, g2, be2);
    // layer 3
    k_gemm_tc<true><<<gemm_blocks, 512, GEMM_SMEM>>>(pagg, pwh + 2 * HH * HH, pwl + 2 * HH * HH);
    k_agg<<<AGG_NB, TB>>>(b3);
    k_stats<<<STAT_NB, TB>>>(2, g3, be3);

    // pool+fc1, then head
    k_poolfc1<<<GG, 128>>>(fcW1, fcb1);
    k_head<<<1, 512>>>(fcg1, fcbe1, fcW2, fcb2, out);
}

// round 10
// speedup vs baseline: 1.6496x; 1.2172x over previous
#include <cuda_runtime.h>
#include <cuda_fp16.h>
#include <cuda_bf16.h>

#define NN 50000
#define EE 800000
#define HH 128
#define GG 500
#define FC1 64
#define EPSBN 1e-5f
#define AGG_NB 6250      /* 50000/8 */
#define STAT_NB 128
#define SCAN_TB 256
#define SCAN_NB 196      /* 196*256 = 50176 >= NN */

// ---------------- device scratch (static, no allocation) ----------------
__device__ __align__(16) unsigned g_h16u[NN * (HH / 2)];  // fp16 messages
__device__ float g_agg[NN * HH];
__device__ int   g_cnt[NN];
__device__ int   g_fill[NN];
__device__ int   g_ptr[NN + 1];
__device__ float g_dis[NN];
__device__ __align__(16) uint2 g_csr[EE];   // packed (src, w)
__device__ int   g_bsum[SCAN_NB];
__device__ int   g_boff[SCAN_NB];
__device__ float g_ps1[AGG_NB * HH];
__device__ float g_pq1[AGG_NB * HH];
__device__ float g_mids[STAT_NB * HH];
__device__ float g_midq[STAT_NB * HH];
__device__ float g_bn_a[HH];
__device__ float g_bn_b[HH];
__device__ int   g_goff[GG + 1];
__device__ float g_z[GG * FC1];
// W pre-split to bf16 hi/lo, transposed & packed: [layer][n][k/2] (k-pairs)
__device__ __align__(16) unsigned g_wt2h[3][HH * (HH / 2)];
__device__ __align__(16) unsigned g_wt2l[3][HH * (HH / 2)];
__device__ int   g_tick;      // scanall ticket
__device__ int   g_flag;      // scanall release flag
__device__ int   g_tick2[3];  // stats tickets (per layer)
__device__ int   g_is64;

// ---------------- helpers ----------------
__device__ __forceinline__ int ld_idx(const void* p, long long i, int is64) {
    return is64 ? (int)(((const long long*)p)[i]) : ((const int*)p)[i];
}

// bf16 hi/lo split of two floats, packed into bf16x2 words (low = first elem)
__device__ __forceinline__ unsigned packsplit(float v0, float v1, unsigned* plo) {
    __nv_bfloat16 h0 = __float2bfloat16(v0);
    __nv_bfloat16 h1 = __float2bfloat16(v1);
    float l0f = v0 - __bfloat162float(h0);
    float l1f = v1 - __bfloat162float(h1);
    __nv_bfloat16 l0 = __float2bfloat16(l0f);
    __nv_bfloat16 l1 = __float2bfloat16(l1f);
    *plo = ((unsigned)__bfloat16_as_ushort(l1) << 16) | __bfloat16_as_ushort(l0);
    return ((unsigned)__bfloat16_as_ushort(h1) << 16) | __bfloat16_as_ushort(h0);
}

// ---------------- pre1: zero + counters + dtype detect + W presplit --------
__global__ void k_pre1(const void* eidx, const float* W1, const float* W2,
                       const float* W3) {
    int i = blockIdx.x * blockDim.x + threadIdx.x;
    if (i < NN) { g_cnt[i] = 0; g_fill[i] = 0; }
    if (i == 0) {
        g_tick = 0; g_flag = 0;
        g_tick2[0] = 0; g_tick2[1] = 0; g_tick2[2] = 0;
    }
    if (blockIdx.x == 0) {
        __shared__ int any;
        if (threadIdx.x == 0) any = 0;
        __syncthreads();
        if (((const int*)eidx)[2 * threadIdx.x + 1] != 0) atomicOr(&any, 1);
        __syncthreads();
        if (threadIdx.x == 0) g_is64 = any ? 0 : 1;
    }
    // W bf16 hi/lo presplit, transposed to [n][k/2]: 3 * 128 * 64 pairs
    if (i < 3 * HH * (HH / 2)) {
        int l = i / (HH * (HH / 2));
        int j = i - l * (HH * (HH / 2));
        int n = j >> 6;          // 0..127
        int kk = j & 63;         // k-pair 0..63
        const float* Wsrc = (l == 0) ? W1 : (l == 1) ? W2 : W3;
        float w0 = Wsrc[(2 * kk) * HH + n];
        float w1 = Wsrc[(2 * kk + 1) * HH + n];
        unsigned lo;
        unsigned hi = packsplit(w0, w1, &lo);
        g_wt2h[l][n * 64 + kk] = hi;
        g_wt2l[l][n * 64 + kk] = lo;
    }
}

// ---------------- count (edge histogram) + graph bounds ----------------
__global__ void k_count(const void* eidx, const void* batch) {
    int e = blockIdx.x * blockDim.x + threadIdx.x;
    int is64 = g_is64;
    if (e < EE) {
        int d = ld_idx(eidx, (long long)EE + e, is64);
        atomicAdd(&g_cnt[d], 1);
    }
    if (e < NN) {
        int b = ld_idx(batch, e, is64);
        int bn = (e + 1 < NN) ? ld_idx(batch, e + 1, is64) : GG;
        if (e == 0)
            for (int g = 0; g <= b && g <= GG; g++) g_goff[g] = 0;
        int hi = bn < GG ? bn : GG;
        for (int g = b + 1; g <= hi; g++) g_goff[g] = e + 1;
    }
}

// ---------------- single-launch CSR scan (ticket + flag spin) ----------------
__global__ void __launch_bounds__(SCAN_TB) k_scanall() {
    __shared__ int sm[SCAN_TB];
    __shared__ int islast;
    int t = threadIdx.x;
    int b = blockIdx.x;
    int i = b * SCAN_TB + t;
    int c = (i < NN) ? g_cnt[i] : 0;
    sm[t] = c;
    __syncthreads();
    for (int off = 1; off < SCAN_TB; off <<= 1) {
        int v = (t >= off) ? sm[t - off] : 0;
        __syncthreads();
        sm[t] += v;
        __syncthreads();
    }
    int local_ex = sm[t] - c;
    int total = sm[SCAN_TB - 1];
    if (t == 0) {
        g_bsum[b] = total;
        __threadfence();
        islast = (atomicAdd(&g_tick, 1) == SCAN_NB - 1);
    }
    __syncthreads();
    if (islast) {
        int v = (t < SCAN_NB) ? g_bsum[t] : 0;
        __syncthreads();
        sm[t] = v;
        __syncthreads();
        for (int off = 1; off < SCAN_TB; off <<= 1) {
            int u = (t >= off) ? sm[t - off] : 0;
            __syncthreads();
            sm[t] += u;
            __syncthreads();
        }
        if (t < SCAN_NB) g_boff[t] = sm[t] - v;
        __threadfence();
        __syncthreads();
        if (t == 0) atomicExch(&g_flag, 1);
    }
    if (t == 0) {
        while (atomicAdd(&g_flag, 0) == 0) __nanosleep(100);
    }
    __syncthreads();
    __threadfence();
    int ex = local_ex + g_boff[b];
    if (i < NN) {
        g_ptr[i] = ex;
        g_dis[i] = rsqrtf((float)(c + 1));
        if (i == NN - 1) g_ptr[NN] = ex + c;
    }
}

__global__ void k_fill(const void* eidx) {
    int e = blockIdx.x * blockDim.x + threadIdx.x;
    if (e >= EE) return;
    int is64 = g_is64;
    int s = ld_idx(eidx, e, is64);
    int d = ld_idx(eidx, (long long)EE + e, is64);
    int pos = atomicAdd(&g_fill[d], 1);
    float w = g_dis[s] * g_dis[d];
    g_csr[g_ptr[d] + pos] = make_uint2((unsigned)s, __float_as_uint(w));
}

// ------- 3xBF16 GEMM via m16n8k16 (packed bf16x2 operands in smem) ---------
// g_h16u[N,128](fp16) = f(X)[N,128] @ W[128,128]; f = id or BN+ReLU.
// 512 thr, warps 4(M)x4(N), warp tile 32x32 (2x4 m16n8k16), k-step 16.
// Numerics: x = xh + xl (bf16 split); acc += xh*wh + xh*wl + xl*wh (~1e-5).
#define P_STRIDE 68    /* 64 bf16x2 pairs + pad (uints) */
#define GEMM_SMEM (4 * 128 * P_STRIDE * 4)

template <bool BN>
__global__ void __launch_bounds__(512, 1) k_gemm_tc(const float* __restrict__ X,
                                                    const unsigned* __restrict__ Wth,
                                                    const unsigned* __restrict__ Wtl) {
    extern __shared__ unsigned usmem[];
    unsigned* Xh2 = usmem;                       // [128][68]
    unsigned* Xl2 = Xh2 + 128 * P_STRIDE;
    unsigned* Wh2 = Xl2 + 128 * P_STRIDE;        // [n=128][68]
    unsigned* Wl2 = Wh2 + 128 * P_STRIDE;
    int tid = threadIdx.x;
    int row0 = blockIdx.x * 128;

    // X tile 128x128 fp32 -> bf16 hi/lo pairs (fused BN+ReLU)
#pragma unroll
    for (int i = 0; i < 8; i++) {
        int q = i * 512 + tid;
        int r = q >> 5;
        int c4 = q & 31;       // float4 index in row
        int gr = row0 + r;
        float4 v = make_float4(0.f, 0.f, 0.f, 0.f);
        if (gr < NN) v = *(const float4*)(X + (size_t)gr * 128 + c4 * 4);
        if (BN) {
            int ch = c4 * 4;
            v.x = fmaxf(g_bn_a[ch + 0] * v.x + g_bn_b[ch + 0], 0.f);
            v.y = fmaxf(g_bn_a[ch + 1] * v.y + g_bn_b[ch + 1], 0.f);
            v.z = fmaxf(g_bn_a[ch + 2] * v.z + g_bn_b[ch + 2], 0.f);
            v.w = fmaxf(g_bn_a[ch + 3] * v.w + g_bn_b[ch + 3], 0.f);
        }
        unsigned lo0, lo1;
        unsigned hi0 = packsplit(v.x, v.y, &lo0);
        unsigned hi1 = packsplit(v.z, v.w, &lo1);
        int o = r * P_STRIDE + c4 * 2;
        Xh2[o] = hi0; Xh2[o + 1] = hi1;
        Xl2[o] = lo0; Xl2[o + 1] = lo1;
    }
    // W hi/lo pair tiles: straight copies (128 rows x 64 uints, src stride 64)
#pragma unroll
    for (int i = 0; i < 4; i++) {
        int q = i * 512 + tid;
        int r = q >> 4;
        int c = (q & 15) * 4;
        *(uint4*)(Wh2 + r * P_STRIDE + c) = *(const uint4*)(Wth + r * 64 + c);
        *(uint4*)(Wl2 + r * P_STRIDE + c) = *(const uint4*)(Wtl + r * 64 + c);
    }
    __syncthreads();

    int wid = tid >> 5;
    int lane = tid & 31;
    int mwid = wid >> 2;
    int nwid = wid & 3;
    int g = lane >> 2;
    int tg = lane & 3;

    float acc[2][4][4];
#pragma unroll
    for (int mi = 0; mi < 2; mi++)
#pragma unroll
        for (int ni = 0; ni < 4; ni++)
#pragma unroll
            for (int j = 0; j < 4; j++) acc[mi][ni][j] = 0.f;

#define MMA16(A0, A1, A2, A3, B0, B1, C)                                \
    asm volatile(                                                       \
        "mma.sync.aligned.m16n8k16.row.col.f32.bf16.bf16.f32 "          \
        "{%0,%1,%2,%3}, {%4,%5,%6,%7}, {%8,%9}, {%0,%1,%2,%3};"         \
        : "+f"(C[0]), "+f"(C[1]), "+f"(C[2]), "+f"(C[3])                \
        : "r"(A0), "r"(A1), "r"(A2), "r"(A3), "r"(B0), "r"(B1))

#pragma unroll
    for (int kp = 0; kp < 64; kp += 8) {   // k-pair offset: k0 = 2*kp, step 16
        unsigned ah[2][4], al[2][4];
#pragma unroll
        for (int mi = 0; mi < 2; mi++) {
            int rb = mwid * 32 + mi * 16;
            int o0 = (rb + g) * P_STRIDE + kp + tg;
            int o1 = (rb + g + 8) * P_STRIDE + kp + tg;
            ah[mi][0] = Xh2[o0];
            ah[mi][1] = Xh2[o1];
            ah[mi][2] = Xh2[o0 + 4];
            ah[mi][3] = Xh2[o1 + 4];
            al[mi][0] = Xl2[o0];
            al[mi][1] = Xl2[o1];
            al[mi][2] = Xl2[o0 + 4];
            al[mi][3] = Xl2[o1 + 4];
        }
#pragma unroll
        for (int ni = 0; ni < 4; ni++) {
            int cb = nwid * 32 + ni * 8;
            int o = (cb + g) * P_STRIDE + kp + tg;
            unsigned bh0 = Wh2[o];
            unsigned bh1 = Wh2[o + 4];
            unsigned bl0 = Wl2[o];
            unsigned bl1 = Wl2[o + 4];
#pragma unroll
            for (int mi = 0; mi < 2; mi++) {
                MMA16(ah[mi][0], ah[mi][1], ah[mi][2], ah[mi][3],
                      bh0, bh1, acc[mi][ni]);
                MMA16(ah[mi][0], ah[mi][1], ah[mi][2], ah[mi][3],
                      bl0, bl1, acc[mi][ni]);
                MMA16(al[mi][0], al[mi][1], al[mi][2], al[mi][3],
                      bh0, bh1, acc[mi][ni]);
            }
        }
    }
#undef MMA16

    // epilogue: fp16 pairs
#pragma unroll
    for (int mi = 0; mi < 2; mi++) {
#pragma unroll
        for (int ni = 0; ni < 4; ni++) {
            int col = nwid * 32 + ni * 8 + tg * 2;
            int r1 = row0 + mwid * 32 + mi * 16 + g;
            int r2 = r1 + 8;
            if (r1 < NN) {
                __half2 h = __floats2half2_rn(acc[mi][ni][0], acc[mi][ni][1]);
                g_h16u[(size_t)r1 * 64 + (col >> 1)] = *(unsigned*)&h;
            }
            if (r2 < NN) {
                __half2 h = __floats2half2_rn(acc[mi][ni][2], acc[mi][ni][3]);
                g_h16u[(size_t)r2 * 64 + (col >> 1)] = *(unsigned*)&h;
            }
        }
    }
}

// ---------------- aggregation (fp16 gather) + fused BN partial stats --------
__global__ void __launch_bounds__(256) k_agg(const float* __restrict__ bias) {
    __shared__ float ps[8][HH];
    __shared__ float pq[8][HH];
    int w = threadIdx.x >> 5;
    int lane = threadIdx.x & 31;
    int d = blockIdx.x * 8 + w;   // NN = 6250*8 exact

    const uint2* Hv = (const uint2*)g_h16u;
    float sd = g_dis[d];
    float ws = sd * sd;
    uint2 u = Hv[(size_t)d * 32 + lane];
    float2 f0 = __half22float2(*(__half2*)&u.x);
    float2 f1 = __half22float2(*(__half2*)&u.y);
    float4 acc = make_float4(f0.x * ws, f0.y * ws, f1.x * ws, f1.y * ws);

    int beg = g_ptr[d], end = g_ptr[d + 1];
    int j = beg;
    for (; j + 4 <= end; j += 4) {
        uint2 e0 = g_csr[j + 0], e1 = g_csr[j + 1];
        uint2 e2 = g_csr[j + 2], e3 = g_csr[j + 3];
        float w0 = __uint_as_float(e0.y), w1 = __uint_as_float(e1.y);
        float w2 = __uint_as_float(e2.y), w3 = __uint_as_float(e3.y);
        uint2 u0 = Hv[(size_t)e0.x * 32 + lane];
        uint2 u1 = Hv[(size_t)e1.x * 32 + lane];
        uint2 u2 = Hv[(size_t)e2.x * 32 + lane];
        uint2 u3 = Hv[(size_t)e3.x * 32 + lane];
        float2 a0, c0;
        a0 = __half22float2(*(__half2*)&u0.x); c0 = __half22float2(*(__half2*)&u0.y);
        acc.x += a0.x * w0; acc.y += a0.y * w0; acc.z += c0.x * w0; acc.w += c0.y * w0;
        a0 = __half22float2(*(__half2*)&u1.x); c0 = __half22float2(*(__half2*)&u1.y);
        acc.x += a0.x * w1; acc.y += a0.y * w1; acc.z += c0.x * w1; acc.w += c0.y * w1;
        a0 = __half22float2(*(__half2*)&u2.x); c0 = __half22float2(*(__half2*)&u2.y);
        acc.x += a0.x * w2; acc.y += a0.y * w2; acc.z += c0.x * w2; acc.w += c0.y * w2;
        a0 = __half22float2(*(__half2*)&u3.x); c0 = __half22float2(*(__half2*)&u3.y);
        acc.x += a0.x * w3; acc.y += a0.y * w3; acc.z += c0.x * w3; acc.w += c0.y * w3;
    }
    for (; j < end; j++) {
        uint2 e = g_csr[j];
        float wj = __uint_as_float(e.y);
        uint2 us = Hv[(size_t)e.x * 32 + lane];
        float2 a0 = __half22float2(*(__half2*)&us.x);
        float2 c0 = __half22float2(*(__half2*)&us.y);
        acc.x += a0.x * wj; acc.y += a0.y * wj; acc.z += c0.x * wj; acc.w += c0.y * wj;
    }
    float4 b4 = ((const float4*)bias)[lane];
    acc.x += b4.x; acc.y += b4.y; acc.z += b4.z; acc.w += b4.w;
    ((float4*)(g_agg + (size_t)d * HH))[lane] = acc;

    int c0i = 4 * lane;
    ps[w][c0i + 0] = acc.x; ps[w][c0i + 1] = acc.y;
    ps[w][c0i + 2] = acc.z; ps[w][c0i + 3] = acc.w;
    pq[w][c0i + 0] = acc.x * acc.x; pq[w][c0i + 1] = acc.y * acc.y;
    pq[w][c0i + 2] = acc.z * acc.z; pq[w][c0i + 3] = acc.w * acc.w;
    __syncthreads();
    int t = threadIdx.x;
    if (t < HH) {
        float s = 0.f;
#pragma unroll
        for (int i = 0; i < 8; i++) s += ps[i][t];
        g_ps1[blockIdx.x * HH + t] = s;
    } else {
        int c = t - HH;
        float s = 0.f;
#pragma unroll
        for (int i = 0; i < 8; i++) s += pq[i][c];
        g_pq1[blockIdx.x * HH + c] = s;
    }
}

// ---------------- BN stats: one launch (mid + ticketed final) ----------------
#define ROWS_PER_STAT 49  /* 128*49 = 6272 >= 6250 */
__global__ void __launch_bounds__(256) k_stats(int which,
                                               const float* __restrict__ gam,
                                               const float* __restrict__ bet) {
    __shared__ int islast;
    int b = blockIdx.x;
    int t = threadIdx.x;
    int c = t & (HH - 1);
    int isq = t >> 7;
    const float* src = isq ? g_pq1 : g_ps1;
    float s = 0.f;
    int r0 = b * ROWS_PER_STAT;
    int r1 = r0 + ROWS_PER_STAT;
    if (r1 > AGG_NB) r1 = AGG_NB;
    for (int r = r0; r < r1; r++) s += src[r * HH + c];
    if (isq) g_midq[b * HH + c] = s;
    else     g_mids[b * HH + c] = s;
    __threadfence();
    if (t == 0) islast = (atomicAdd(&g_tick2[which], 1) == STAT_NB - 1);
    __syncthreads();
    if (!islast) return;
    if (t < HH) {
        float su = 0.f, q = 0.f;
        for (int b2 = 0; b2 < STAT_NB; b2++) {
            su += g_mids[b2 * HH + t];
            q  += g_midq[b2 * HH + t];
        }
        float m = su / (float)NN;
        float var = q / (float)NN - m * m;
        float a = gam[t] * rsqrtf(var + EPSBN);
        g_bn_a[t] = a;
        g_bn_b[t] = bet[t] - m * a;
    }
}

// ---------------- pool (BN3+ReLU fused) + FC1, one kernel ----------------
__global__ void __launch_bounds__(128) k_poolfc1(const float* __restrict__ Wf,
                                                 const float* __restrict__ bf) {
    __shared__ float pooled[HH];
    int gI = blockIdx.x;
    int c = threadIdx.x;
    int beg = g_goff[gI], end = g_goff[gI + 1];
    float a = g_bn_a[c], b = g_bn_b[c];
    float acc = 0.f;
    for (int r = beg; r < end; r++) {
        float v = g_agg[(size_t)r * HH + c];
        acc += fmaxf(a * v + b, 0.f);
    }
    float cnt = (float)(end - beg);
    pooled[c] = acc / fmaxf(cnt, 1.f);
    __syncthreads();
    if (c < FC1) {
        float s = bf[c];
#pragma unroll 8
        for (int k = 0; k < HH; k++) s += pooled[k] * Wf[k * FC1 + c];
        g_z[gI * FC1 + c] = s;
    }
}

// ---------------- head: fc BN stats + fc2, one block ----------------
__global__ void __launch_bounds__(512) k_head(const float* __restrict__ gam,
                                              const float* __restrict__ bet,
                                              const float* __restrict__ W2f,
                                              const float* __restrict__ b2f,
                                              float* __restrict__ out) {
    __shared__ float fa[FC1], fb[FC1];
    int t = threadIdx.x;
    if (t < FC1) {
        float s = 0.f, q = 0.f;
#pragma unroll 4
        for (int r = 0; r < GG; r++) {
            float v = g_z[r * FC1 + t];
            s += v;
            q += v * v;
        }
        float m = s / (float)GG;
        float var = q / (float)GG - m * m;
        float a = gam[t] * rsqrtf(var + EPSBN);
        fa[t] = a;
        fb[t] = bet[t] - m * a;
    }
    __syncthreads();
    if (t < GG) {
        float s = b2f[0];
#pragma unroll 8
        for (int c = 0; c < FC1; c++) {
            float v = g_z[t * FC1 + c];
            v = fmaxf(fa[c] * v + fb[c], 0.f);
            s += v * W2f[c];
        }
        out[t] = s;
    }
}

// ---------------- launch ----------------
extern "C" void kernel_launch(void* const* d_in, const int* in_sizes, int n_in,
                              void* d_out, int out_size) {
    const float* x    = (const float*)d_in[0];
    const void*  eidx = d_in[1];
    const void*  batc = d_in[2];
    const float* W1 = (const float*)d_in[3];
    const float* b1 = (const float*)d_in[4];
    const float* g1 = (const float*)d_in[5];
    const float* be1 = (const float*)d_in[6];
    const float* W2 = (const float*)d_in[7];
    const float* b2 = (const float*)d_in[8];
    const float* g2 = (const float*)d_in[9];
    const float* be2 = (const float*)d_in[10];
    const float* W3 = (const float*)d_in[11];
    const float* b3 = (const float*)d_in[12];
    const float* g3 = (const float*)d_in[13];
    const float* be3 = (const float*)d_in[14];
    const float* fcW1 = (const float*)d_in[15];
    const float* fcb1 = (const float*)d_in[16];
    const float* fcg1 = (const float*)d_in[17];
    const float* fcbe1 = (const float*)d_in[18];
    const float* fcW2 = (const float*)d_in[19];
    const float* fcb2 = (const float*)d_in[20];
    float* out = (float*)d_out;

    float* pagg = nullptr;
    unsigned *pwth = nullptr, *pwtl = nullptr;
    cudaGetSymbolAddress((void**)&pagg, g_agg);
    cudaGetSymbolAddress((void**)&pwth, g_wt2h);
    cudaGetSymbolAddress((void**)&pwtl, g_wt2l);

    const int TB = 256;
    const int gemm_blocks = (NN + 127) / 128;
    const int WSZ = HH * (HH / 2);   // uints per layer in g_wt2h/l

    static int init_done = 0;
    if (!init_done) {
        cudaFuncSetAttribute(k_gemm_tc<false>,
                             cudaFuncAttributeMaxDynamicSharedMemorySize, GEMM_SMEM);
        cudaFuncSetAttribute(k_gemm_tc<true>,
                             cudaFuncAttributeMaxDynamicSharedMemorySize, GEMM_SMEM);
        init_done = 1;
    }

    k_pre1<<<SCAN_NB, TB>>>(eidx, W1, W2, W3);
    k_count<<<(EE + TB - 1) / TB, TB>>>(eidx, batc);
    k_scanall<<<SCAN_NB, SCAN_TB>>>();
    k_fill<<<(EE + TB - 1) / TB, TB>>>(eidx);

    // layer 1
    k_gemm_tc<false><<<gemm_blocks, 512, GEMM_SMEM>>>(x, pwth, pwtl);
    k_agg<<<AGG_NB, TB>>>(b1);
    k_stats<<<STAT_NB, TB>>>(0, g1, be1);
    // layer 2
    k_gemm_tc<true><<<gemm_blocks, 512, GEMM_SMEM>>>(pagg, pwth + WSZ, pwtl + WSZ);
    k_agg<<<AGG_NB, TB>>>(b2);
    k_stats<<<STAT_NB, TB>>>(1, g2, be2);
    // layer 3
    k_gemm_tc<true><<<gemm_blocks, 512, GEMM_SMEM>>>(pagg, pwth + 2 * WSZ, pwtl + 2 * WSZ);
    k_agg<<<AGG_NB, TB>>>(b3);
    k_stats<<<STAT_NB, TB>>>(2, g3, be3);

    // pool+fc1, then head
    k_poolfc1<<<GG, 128>>>(fcW1, fcb1);
    k_head<<<1, 512>>>(fcg1, fcbe1, fcW2, fcb2, out);
}

// round 11
// speedup vs baseline: 1.6641x; 1.0088x over previous
#include <cuda_runtime.h>
#include <cuda_fp16.h>
#include <cuda_bf16.h>

#define NN 50000
#define EE 800000
#define HH 128
#define GG 500
#define FC1 64
#define EPSBN 1e-5f
#define AGG_NB 6250      /* 50000/8 */
#define STAT_NB 128
#define SCAN_TB 256
#define SCAN_NB 196      /* 196*256 = 50176 >= NN */

// ---------------- device scratch (static, no allocation) ----------------
__device__ __align__(16) unsigned g_h16u[NN * (HH / 2)];  // fp16 messages
__device__ float g_agg[NN * HH];
__device__ int   g_cnt[NN];
__device__ int   g_fill[NN];
__device__ int   g_ptr[NN + 1];
__device__ float g_dis[NN];
__device__ __align__(16) uint2 g_csr[EE];   // packed (src, w)
__device__ int   g_bsum[SCAN_NB];
__device__ int   g_boff[SCAN_NB];
__device__ float g_ps1[AGG_NB * HH];
__device__ float g_pq1[AGG_NB * HH];
__device__ float g_mids[STAT_NB * HH];
__device__ float g_midq[STAT_NB * HH];
__device__ float g_bn_a[HH];
__device__ float g_bn_b[HH];
__device__ int   g_goff[GG + 1];
__device__ float g_z[GG * FC1];
// W pre-split to bf16 hi/lo, transposed & packed: [layer][n][k/2] (k-pairs)
__device__ __align__(16) unsigned g_wt2h[3][HH * (HH / 2)];
__device__ __align__(16) unsigned g_wt2l[3][HH * (HH / 2)];
__device__ int   g_tick;      // scanall ticket
__device__ int   g_flag;      // scanall release flag
__device__ int   g_tick2[3];  // stats tickets (per layer)
__device__ int   g_is64;

// ---------------- helpers ----------------
__device__ __forceinline__ int ld_idx(const void* p, long long i, int is64) {
    return is64 ? (int)(((const long long*)p)[i]) : ((const int*)p)[i];
}

// bf16 hi/lo split of two floats, packed into bf16x2 words (low = first elem)
__device__ __forceinline__ unsigned packsplit(float v0, float v1, unsigned* plo) {
    __nv_bfloat16 h0 = __float2bfloat16(v0);
    __nv_bfloat16 h1 = __float2bfloat16(v1);
    float l0f = v0 - __bfloat162float(h0);
    float l1f = v1 - __bfloat162float(h1);
    __nv_bfloat16 l0 = __float2bfloat16(l0f);
    __nv_bfloat16 l1 = __float2bfloat16(l1f);
    *plo = ((unsigned)__bfloat16_as_ushort(l1) << 16) | __bfloat16_as_ushort(l0);
    return ((unsigned)__bfloat16_as_ushort(h1) << 16) | __bfloat16_as_ushort(h0);
}

// ---------------- pre1: zero + counters + dtype detect + W presplit --------
__global__ void k_pre1(const void* eidx, const float* W1, const float* W2,
                       const float* W3) {
    int i = blockIdx.x * blockDim.x + threadIdx.x;
    if (i < NN) { g_cnt[i] = 0; g_fill[i] = 0; }
    if (i == 0) {
        g_tick = 0; g_flag = 0;
        g_tick2[0] = 0; g_tick2[1] = 0; g_tick2[2] = 0;
    }
    if (blockIdx.x == 0) {
        __shared__ int any;
        if (threadIdx.x == 0) any = 0;
        __syncthreads();
        if (((const int*)eidx)[2 * threadIdx.x + 1] != 0) atomicOr(&any, 1);
        __syncthreads();
        if (threadIdx.x == 0) g_is64 = any ? 0 : 1;
    }
    // W bf16 hi/lo presplit, transposed to [n][k/2]: 3 * 128 * 64 pairs
    if (i < 3 * HH * (HH / 2)) {
        int l = i / (HH * (HH / 2));
        int j = i - l * (HH * (HH / 2));
        int n = j >> 6;          // 0..127
        int kk = j & 63;         // k-pair 0..63
        const float* Wsrc = (l == 0) ? W1 : (l == 1) ? W2 : W3;
        float w0 = Wsrc[(2 * kk) * HH + n];
        float w1 = Wsrc[(2 * kk + 1) * HH + n];
        unsigned lo;
        unsigned hi = packsplit(w0, w1, &lo);
        g_wt2h[l][n * 64 + kk] = hi;
        g_wt2l[l][n * 64 + kk] = lo;
    }
}

// ------ count (edge histogram, 4 edges/thread) + graph bounds ------
__global__ void k_count(const void* eidx, const void* batch) {
    int idx = blockIdx.x * blockDim.x + threadIdx.x;
    int is64 = g_is64;
    int e4 = idx * 4;
    if (e4 < EE) {
        int d0, d1, d2, d3;
        if (is64) {
            const long long* p = (const long long*)eidx + EE + e4;
            longlong2 a = *(const longlong2*)p;
            longlong2 b = *(const longlong2*)(p + 2);
            d0 = (int)a.x; d1 = (int)a.y; d2 = (int)b.x; d3 = (int)b.y;
        } else {
            int4 a = *(const int4*)((const int*)eidx + EE + e4);
            d0 = a.x; d1 = a.y; d2 = a.z; d3 = a.w;
        }
        atomicAdd(&g_cnt[d0], 1);
        atomicAdd(&g_cnt[d1], 1);
        atomicAdd(&g_cnt[d2], 1);
        atomicAdd(&g_cnt[d3], 1);
    }
    int i = idx;
    if (i < NN) {
        int b = ld_idx(batch, i, is64);
        int bn = (i + 1 < NN) ? ld_idx(batch, i + 1, is64) : GG;
        if (i == 0)
            for (int g = 0; g <= b && g <= GG; g++) g_goff[g] = 0;
        int hi = bn < GG ? bn : GG;
        for (int g = b + 1; g <= hi; g++) g_goff[g] = i + 1;
    }
}

// ---------------- single-launch CSR scan (ticket + flag spin) ----------------
__global__ void __launch_bounds__(SCAN_TB) k_scanall() {
    __shared__ int sm[SCAN_TB];
    __shared__ int islast;
    int t = threadIdx.x;
    int b = blockIdx.x;
    int i = b * SCAN_TB + t;
    int c = (i < NN) ? g_cnt[i] : 0;
    sm[t] = c;
    __syncthreads();
    for (int off = 1; off < SCAN_TB; off <<= 1) {
        int v = (t >= off) ? sm[t - off] : 0;
        __syncthreads();
        sm[t] += v;
        __syncthreads();
    }
    int local_ex = sm[t] - c;
    int total = sm[SCAN_TB - 1];
    if (t == 0) {
        g_bsum[b] = total;
        __threadfence();
        islast = (atomicAdd(&g_tick, 1) == SCAN_NB - 1);
    }
    __syncthreads();
    if (islast) {
        int v = (t < SCAN_NB) ? g_bsum[t] : 0;
        __syncthreads();
        sm[t] = v;
        __syncthreads();
        for (int off = 1; off < SCAN_TB; off <<= 1) {
            int u = (t >= off) ? sm[t - off] : 0;
            __syncthreads();
            sm[t] += u;
            __syncthreads();
        }
        if (t < SCAN_NB) g_boff[t] = sm[t] - v;
        __threadfence();
        __syncthreads();
        if (t == 0) atomicExch(&g_flag, 1);
    }
    if (t == 0) {
        while (atomicAdd(&g_flag, 0) == 0) __nanosleep(100);
    }
    __syncthreads();
    __threadfence();
    int ex = local_ex + g_boff[b];
    if (i < NN) {
        g_ptr[i] = ex;
        g_dis[i] = rsqrtf((float)(c + 1));
        if (i == NN - 1) g_ptr[NN] = ex + c;
    }
}

// ---------------- CSR fill, 4 edges/thread ----------------
__global__ void k_fill(const void* eidx) {
    int idx = blockIdx.x * blockDim.x + threadIdx.x;
    int e4 = idx * 4;
    if (e4 >= EE) return;
    int is64 = g_is64;
    int s0, s1, s2, s3, d0, d1, d2, d3;
    if (is64) {
        const long long* ps = (const long long*)eidx + e4;
        const long long* pd = (const long long*)eidx + EE + e4;
        longlong2 a = *(const longlong2*)ps;
        longlong2 b = *(const longlong2*)(ps + 2);
        longlong2 c = *(const longlong2*)pd;
        longlong2 e = *(const longlong2*)(pd + 2);
        s0 = (int)a.x; s1 = (int)a.y; s2 = (int)b.x; s3 = (int)b.y;
        d0 = (int)c.x; d1 = (int)c.y; d2 = (int)e.x; d3 = (int)e.y;
    } else {
        int4 a = *(const int4*)((const int*)eidx + e4);
        int4 c = *(const int4*)((const int*)eidx + EE + e4);
        s0 = a.x; s1 = a.y; s2 = a.z; s3 = a.w;
        d0 = c.x; d1 = c.y; d2 = c.z; d3 = c.w;
    }
    float q0 = g_dis[s0], q1 = g_dis[s1], q2 = g_dis[s2], q3 = g_dis[s3];
    int p0 = atomicAdd(&g_fill[d0], 1);
    int p1 = atomicAdd(&g_fill[d1], 1);
    int p2 = atomicAdd(&g_fill[d2], 1);
    int p3 = atomicAdd(&g_fill[d3], 1);
    g_csr[g_ptr[d0] + p0] = make_uint2((unsigned)s0, __float_as_uint(q0 * g_dis[d0]));
    g_csr[g_ptr[d1] + p1] = make_uint2((unsigned)s1, __float_as_uint(q1 * g_dis[d1]));
    g_csr[g_ptr[d2] + p2] = make_uint2((unsigned)s2, __float_as_uint(q2 * g_dis[d2]));
    g_csr[g_ptr[d3] + p3] = make_uint2((unsigned)s3, __float_as_uint(q3 * g_dis[d3]));
}

// ------- persistent 3xBF16 GEMM: W resident, double-buffered X prefetch ----
// g_h16u[N,128](fp16) = f(X)[N,128] @ W[128,128]; f = id or BN+ReLU.
// 148 blocks x 512 thr; warps 4(M)x4(N); warp tile 32x32 (2x4 m16n8k16).
#define P_STRIDE 68    /* 64 bf16x2 pairs + pad (uints) */
#define XBUF (2 * 128 * P_STRIDE)
#define GEMM_SMEM ((2 * 128 * P_STRIDE + 2 * XBUF) * 4)   /* ~209 KB */
#define GEMM_TILES ((NN + 127) / 128)
#define GEMM_BLK 148

template <bool BN>
__global__ void __launch_bounds__(512, 1) k_gemm_tc(const float* __restrict__ X,
                                                    const unsigned* __restrict__ Wth,
                                                    const unsigned* __restrict__ Wtl) {
    extern __shared__ unsigned usmem[];
    unsigned* Wh2 = usmem;                      // [128][68]
    unsigned* Wl2 = Wh2 + 128 * P_STRIDE;
    unsigned* Xb  = Wl2 + 128 * P_STRIDE;       // [2][2][128*68]
    int tid = threadIdx.x;
    int b = blockIdx.x;

    int wid = tid >> 5;
    int lane = tid & 31;
    int mwid = wid >> 2;
    int nwid = wid & 3;
    int g = lane >> 2;
    int tg = lane & 3;
    // per-thread load mapping (8 float4 per tile)
    int lr[8], lc4[8];
#pragma unroll
    for (int i = 0; i < 8; i++) {
        int q = i * 512 + tid;
        lr[i] = q >> 5;
        lc4[i] = q & 31;
    }

    // W resident load (once)
#pragma unroll
    for (int i = 0; i < 4; i++) {
        int q = i * 512 + tid;
        int r = q >> 4;
        int c = (q & 15) * 4;
        *(uint4*)(Wh2 + r * P_STRIDE + c) = *(const uint4*)(Wth + r * 64 + c);
        *(uint4*)(Wl2 + r * P_STRIDE + c) = *(const uint4*)(Wtl + r * 64 + c);
    }

#define LOADX(TILE, PF)                                                     \
    do {                                                                    \
        int row0p = (TILE) * 128;                                           \
        _Pragma("unroll") for (int i = 0; i < 8; i++) {                     \
            int gr = row0p + lr[i];                                         \
            PF[i] = make_float4(0.f, 0.f, 0.f, 0.f);                        \
            if (gr < NN) PF[i] = *(const float4*)(X + (size_t)gr * 128 + lc4[i] * 4); \
        }                                                                   \
    } while (0)

#define STOREX(BUF, PF)                                                     \
    do {                                                                    \
        _Pragma("unroll") for (int i = 0; i < 8; i++) {                     \
            float4 v = PF[i];                                               \
            if (BN) {                                                       \
                int ch = lc4[i] * 4;                                        \
                v.x = fmaxf(g_bn_a[ch + 0] * v.x + g_bn_b[ch + 0], 0.f);    \
                v.y = fmaxf(g_bn_a[ch + 1] * v.y + g_bn_b[ch + 1], 0.f);    \
                v.z = fmaxf(g_bn_a[ch + 2] * v.z + g_bn_b[ch + 2], 0.f);    \
                v.w = fmaxf(g_bn_a[ch + 3] * v.w + g_bn_b[ch + 3], 0.f);    \
            }                                                               \
            unsigned lo0, lo1;                                              \
            unsigned hi0 = packsplit(v.x, v.y, &lo0);                       \
            unsigned hi1 = packsplit(v.z, v.w, &lo1);                       \
            int o = lr[i] * P_STRIDE + lc4[i] * 2;                          \
            (BUF)[o] = hi0; (BUF)[o + 1] = hi1;                             \
            (BUF)[o + 128 * P_STRIDE] = lo0;                                \
            (BUF)[o + 128 * P_STRIDE + 1] = lo1;                            \
        }                                                                   \
    } while (0)

#define MMA16(A0, A1, A2, A3, B0, B1, C)                                \
    asm volatile(                                                       \
        "mma.sync.aligned.m16n8k16.row.col.f32.bf16.bf16.f32 "          \
        "{%0,%1,%2,%3}, {%4,%5,%6,%7}, {%8,%9}, {%0,%1,%2,%3};"         \
        : "+f"(C[0]), "+f"(C[1]), "+f"(C[2]), "+f"(C[3])                \
        : "r"(A0), "r"(A1), "r"(A2), "r"(A3), "r"(B0), "r"(B1))

    // prologue: tile b into buf 0
    {
        float4 pf[8];
        LOADX(b, pf);
        STOREX(Xb, pf);
    }
    __syncthreads();

    int nt = 0;
    for (int tile = b; tile < GEMM_TILES; tile += GEMM_BLK, nt++) {
        int cur = nt & 1;
        unsigned* Xh2 = Xb + cur * XBUF;
        unsigned* Xl2 = Xh2 + 128 * P_STRIDE;
        int row0 = tile * 128;
        int next = tile + GEMM_BLK;

        // prefetch next tile into registers (overlaps with MMAs below)
        float4 pf[8];
        if (next < GEMM_TILES) LOADX(next, pf);

        float acc[2][4][4];
#pragma unroll
        for (int mi = 0; mi < 2; mi++)
#pragma unroll
            for (int ni = 0; ni < 4; ni++)
#pragma unroll
                for (int j = 0; j < 4; j++) acc[mi][ni][j] = 0.f;

#pragma unroll
        for (int kp = 0; kp < 64; kp += 8) {
            unsigned ah[2][4], al[2][4];
#pragma unroll
            for (int mi = 0; mi < 2; mi++) {
                int rb = mwid * 32 + mi * 16;
                int o0 = (rb + g) * P_STRIDE + kp + tg;
                int o1 = (rb + g + 8) * P_STRIDE + kp + tg;
                ah[mi][0] = Xh2[o0];
                ah[mi][1] = Xh2[o1];
                ah[mi][2] = Xh2[o0 + 4];
                ah[mi][3] = Xh2[o1 + 4];
                al[mi][0] = Xl2[o0];
                al[mi][1] = Xl2[o1];
                al[mi][2] = Xl2[o0 + 4];
                al[mi][3] = Xl2[o1 + 4];
            }
#pragma unroll
            for (int ni = 0; ni < 4; ni++) {
                int cb = nwid * 32 + ni * 8;
                int o = (cb + g) * P_STRIDE + kp + tg;
                unsigned bh0 = Wh2[o];
                unsigned bh1 = Wh2[o + 4];
                unsigned bl0 = Wl2[o];
                unsigned bl1 = Wl2[o + 4];
#pragma unroll
                for (int mi = 0; mi < 2; mi++) {
                    MMA16(ah[mi][0], ah[mi][1], ah[mi][2], ah[mi][3],
                          bh0, bh1, acc[mi][ni]);
                    MMA16(ah[mi][0], ah[mi][1], ah[mi][2], ah[mi][3],
                          bl0, bl1, acc[mi][ni]);
                    MMA16(al[mi][0], al[mi][1], al[mi][2], al[mi][3],
                          bh0, bh1, acc[mi][ni]);
                }
            }
        }

        // store prefetched tile into alternate buffer (safe: its last readers
        // synced at end of previous iteration)
        if (next < GEMM_TILES) STOREX(Xb + (cur ^ 1) * XBUF, pf);

        // epilogue: fp16 pairs
#pragma unroll
        for (int mi = 0; mi < 2; mi++) {
#pragma unroll
            for (int ni = 0; ni < 4; ni++) {
                int col = nwid * 32 + ni * 8 + tg * 2;
                int r1 = row0 + mwid * 32 + mi * 16 + g;
                int r2 = r1 + 8;
                if (r1 < NN) {
                    __half2 h = __floats2half2_rn(acc[mi][ni][0], acc[mi][ni][1]);
                    g_h16u[(size_t)r1 * 64 + (col >> 1)] = *(unsigned*)&h;
                }
                if (r2 < NN) {
                    __half2 h = __floats2half2_rn(acc[mi][ni][2], acc[mi][ni][3]);
                    g_h16u[(size_t)r2 * 64 + (col >> 1)] = *(unsigned*)&h;
                }
            }
        }
        __syncthreads();
    }
#undef MMA16
#undef LOADX
#undef STOREX
}

// ---------------- aggregation (fp16 gather) + fused BN partial stats --------
__global__ void __launch_bounds__(256) k_agg(const float* __restrict__ bias) {
    __shared__ float ps[8][HH];
    __shared__ float pq[8][HH];
    int w = threadIdx.x >> 5;
    int lane = threadIdx.x & 31;
    int d = blockIdx.x * 8 + w;   // NN = 6250*8 exact

    const uint2* Hv = (const uint2*)g_h16u;
    float sd = g_dis[d];
    float ws = sd * sd;
    uint2 u = Hv[(size_t)d * 32 + lane];
    float2 f0 = __half22float2(*(__half2*)&u.x);
    float2 f1 = __half22float2(*(__half2*)&u.y);
    float4 acc = make_float4(f0.x * ws, f0.y * ws, f1.x * ws, f1.y * ws);

    int beg = g_ptr[d], end = g_ptr[d + 1];
    int j = beg;
    for (; j + 4 <= end; j += 4) {
        uint2 e0 = g_csr[j + 0], e1 = g_csr[j + 1];
        uint2 e2 = g_csr[j + 2], e3 = g_csr[j + 3];
        float w0 = __uint_as_float(e0.y), w1 = __uint_as_float(e1.y);
        float w2 = __uint_as_float(e2.y), w3 = __uint_as_float(e3.y);
        uint2 u0 = Hv[(size_t)e0.x * 32 + lane];
        uint2 u1 = Hv[(size_t)e1.x * 32 + lane];
        uint2 u2 = Hv[(size_t)e2.x * 32 + lane];
        uint2 u3 = Hv[(size_t)e3.x * 32 + lane];
        float2 a0, c0;
        a0 = __half22float2(*(__half2*)&u0.x); c0 = __half22float2(*(__half2*)&u0.y);
        acc.x += a0.x * w0; acc.y += a0.y * w0; acc.z += c0.x * w0; acc.w += c0.y * w0;
        a0 = __half22float2(*(__half2*)&u1.x); c0 = __half22float2(*(__half2*)&u1.y);
        acc.x += a0.x * w1; acc.y += a0.y * w1; acc.z += c0.x * w1; acc.w += c0.y * w1;
        a0 = __half22float2(*(__half2*)&u2.x); c0 = __half22float2(*(__half2*)&u2.y);
        acc.x += a0.x * w2; acc.y += a0.y * w2; acc.z += c0.x * w2; acc.w += c0.y * w2;
        a0 = __half22float2(*(__half2*)&u3.x); c0 = __half22float2(*(__half2*)&u3.y);
        acc.x += a0.x * w3; acc.y += a0.y * w3; acc.z += c0.x * w3; acc.w += c0.y * w3;
    }
    for (; j < end; j++) {
        uint2 e = g_csr[j];
        float wj = __uint_as_float(e.y);
        uint2 us = Hv[(size_t)e.x * 32 + lane];
        float2 a0 = __half22float2(*(__half2*)&us.x);
        float2 c0 = __half22float2(*(__half2*)&us.y);
        acc.x += a0.x * wj; acc.y += a0.y * wj; acc.z += c0.x * wj; acc.w += c0.y * wj;
    }
    float4 b4 = ((const float4*)bias)[lane];
    acc.x += b4.x; acc.y += b4.y; acc.z += b4.z; acc.w += b4.w;
    ((float4*)(g_agg + (size_t)d * HH))[lane] = acc;

    int c0i = 4 * lane;
    ps[w][c0i + 0] = acc.x; ps[w][c0i + 1] = acc.y;
    ps[w][c0i + 2] = acc.z; ps[w][c0i + 3] = acc.w;
    pq[w][c0i + 0] = acc.x * acc.x; pq[w][c0i + 1] = acc.y * acc.y;
    pq[w][c0i + 2] = acc.z * acc.z; pq[w][c0i + 3] = acc.w * acc.w;
    __syncthreads();
    int t = threadIdx.x;
    if (t < HH) {
        float s = 0.f;
#pragma unroll
        for (int i = 0; i < 8; i++) s += ps[i][t];
        g_ps1[blockIdx.x * HH + t] = s;
    } else {
        int c = t - HH;
        float s = 0.f;
#pragma unroll
        for (int i = 0; i < 8; i++) s += pq[i][c];
        g_pq1[blockIdx.x * HH + c] = s;
    }
}

// ---------------- BN stats: one launch (mid + ticketed final) ----------------
#define ROWS_PER_STAT 49  /* 128*49 = 6272 >= 6250 */
__global__ void __launch_bounds__(256) k_stats(int which,
                                               const float* __restrict__ gam,
                                               const float* __restrict__ bet) {
    __shared__ int islast;
    int b = blockIdx.x;
    int t = threadIdx.x;
    int c = t & (HH - 1);
    int isq = t >> 7;
    const float* src = isq ? g_pq1 : g_ps1;
    float s = 0.f;
    int r0 = b * ROWS_PER_STAT;
    int r1 = r0 + ROWS_PER_STAT;
    if (r1 > AGG_NB) r1 = AGG_NB;
    for (int r = r0; r < r1; r++) s += src[r * HH + c];
    if (isq) g_midq[b * HH + c] = s;
    else     g_mids[b * HH + c] = s;
    __threadfence();
    if (t == 0) islast = (atomicAdd(&g_tick2[which], 1) == STAT_NB - 1);
    __syncthreads();
    if (!islast) return;
    if (t < HH) {
        float su = 0.f, q = 0.f;
        for (int b2 = 0; b2 < STAT_NB; b2++) {
            su += g_mids[b2 * HH + t];
            q  += g_midq[b2 * HH + t];
        }
        float m = su / (float)NN;
        float var = q / (float)NN - m * m;
        float a = gam[t] * rsqrtf(var + EPSBN);
        g_bn_a[t] = a;
        g_bn_b[t] = bet[t] - m * a;
    }
}

// ---------------- pool (BN3+ReLU fused) + FC1, one kernel ----------------
__global__ void __launch_bounds__(128) k_poolfc1(const float* __restrict__ Wf,
                                                 const float* __restrict__ bf) {
    __shared__ float pooled[HH];
    int gI = blockIdx.x;
    int c = threadIdx.x;
    int beg = g_goff[gI], end = g_goff[gI + 1];
    float a = g_bn_a[c], b = g_bn_b[c];
    float acc = 0.f;
    for (int r = beg; r < end; r++) {
        float v = g_agg[(size_t)r * HH + c];
        acc += fmaxf(a * v + b, 0.f);
    }
    float cnt = (float)(end - beg);
    pooled[c] = acc / fmaxf(cnt, 1.f);
    __syncthreads();
    if (c < FC1) {
        float s = bf[c];
#pragma unroll 8
        for (int k = 0; k < HH; k++) s += pooled[k] * Wf[k * FC1 + c];
        g_z[gI * FC1 + c] = s;
    }
}

// ---------------- head: fc BN stats + fc2, one block ----------------
__global__ void __launch_bounds__(512) k_head(const float* __restrict__ gam,
                                              const float* __restrict__ bet,
                                              const float* __restrict__ W2f,
                                              const float* __restrict__ b2f,
                                              float* __restrict__ out) {
    __shared__ float fa[FC1], fb[FC1];
    int t = threadIdx.x;
    if (t < FC1) {
        float s = 0.f, q = 0.f;
#pragma unroll 4
        for (int r = 0; r < GG; r++) {
            float v = g_z[r * FC1 + t];
            s += v;
            q += v * v;
        }
        float m = s / (float)GG;
        float var = q / (float)GG - m * m;
        float a = gam[t] * rsqrtf(var + EPSBN);
        fa[t] = a;
        fb[t] = bet[t] - m * a;
    }
    __syncthreads();
    if (t < GG) {
        float s = b2f[0];
#pragma unroll 8
        for (int c = 0; c < FC1; c++) {
            float v = g_z[t * FC1 + c];
            v = fmaxf(fa[c] * v + fb[c], 0.f);
            s += v * W2f[c];
        }
        out[t] = s;
    }
}

// ---------------- launch ----------------
extern "C" void kernel_launch(void* const* d_in, const int* in_sizes, int n_in,
                              void* d_out, int out_size) {
    const float* x    = (const float*)d_in[0];
    const void*  eidx = d_in[1];
    const void*  batc = d_in[2];
    const float* W1 = (const float*)d_in[3];
    const float* b1 = (const float*)d_in[4];
    const float* g1 = (const float*)d_in[5];
    const float* be1 = (const float*)d_in[6];
    const float* W2 = (const float*)d_in[7];
    const float* b2 = (const float*)d_in[8];
    const float* g2 = (const float*)d_in[9];
    const float* be2 = (const float*)d_in[10];
    const float* W3 = (const float*)d_in[11];
    const float* b3 = (const float*)d_in[12];
    const float* g3 = (const float*)d_in[13];
    const float* be3 = (const float*)d_in[14];
    const float* fcW1 = (const float*)d_in[15];
    const float* fcb1 = (const float*)d_in[16];
    const float* fcg1 = (const float*)d_in[17];
    const float* fcbe1 = (const float*)d_in[18];
    const float* fcW2 = (const float*)d_in[19];
    const float* fcb2 = (const float*)d_in[20];
    float* out = (float*)d_out;

    float* pagg = nullptr;
    unsigned *pwth = nullptr, *pwtl = nullptr;
    cudaGetSymbolAddress((void**)&pagg, g_agg);
    cudaGetSymbolAddress((void**)&pwth, g_wt2h);
    cudaGetSymbolAddress((void**)&pwtl, g_wt2l);

    const int TB = 256;
    const int WSZ = HH * (HH / 2);   // uints per layer in g_wt2h/l

    static int init_done = 0;
    if (!init_done) {
        cudaFuncSetAttribute(k_gemm_tc<false>,
                             cudaFuncAttributeMaxDynamicSharedMemorySize, GEMM_SMEM);
        cudaFuncSetAttribute(k_gemm_tc<true>,
                             cudaFuncAttributeMaxDynamicSharedMemorySize, GEMM_SMEM);
        init_done = 1;
    }

    k_pre1<<<SCAN_NB, TB>>>(eidx, W1, W2, W3);
    k_count<<<(EE / 4 + TB - 1) / TB, TB>>>(eidx, batc);
    k_scanall<<<SCAN_NB, SCAN_TB>>>();
    k_fill<<<(EE / 4 + TB - 1) / TB, TB>>>(eidx);

    // layer 1
    k_gemm_tc<false><<<GEMM_BLK, 512, GEMM_SMEM>>>(x, pwth, pwtl);
    k_agg<<<AGG_NB, TB>>>(b1);
    k_stats<<<STAT_NB, TB>>>(0, g1, be1);
    // layer 2
    k_gemm_tc<true><<<GEMM_BLK, 512, GEMM_SMEM>>>(pagg, pwth + WSZ, pwtl + WSZ);
    k_agg<<<AGG_NB, TB>>>(b2);
    k_stats<<<STAT_NB, TB>>>(1, g2, be2);
    // layer 3
    k_gemm_tc<true><<<GEMM_BLK, 512, GEMM_SMEM>>>(pagg, pwth + 2 * WSZ, pwtl + 2 * WSZ);
    k_agg<<<AGG_NB, TB>>>(b3);
    k_stats<<<STAT_NB, TB>>>(2, g3, be3);

    // pool+fc1, then head
    k_poolfc1<<<GG, 128>>>(fcW1, fcb1);
    k_head<<<1, 512>>>(fcg1, fcbe1, fcW2, fcb2, out);
}

// round 13
// speedup vs baseline: 1.7055x; 1.0249x over previous
#include <cuda_runtime.h>
#include <cuda_fp16.h>
#include <cuda_bf16.h>

#define NN 50000
#define EE 800000
#define HH 128
#define GG 500
#define FC1 64
#define EPSBN 1e-5f
#define AGG_NB 6250      /* 50000/8 */
#define STAT_NB 128
#define SCAN_TB 256
#define SCAN_NB 196      /* 196*256 = 50176 >= NN */

// ---------------- device scratch (static, no allocation) ----------------
__device__ __align__(16) unsigned g_h16u[NN * (HH / 2)];  // fp16 messages
__device__ float g_agg[NN * HH];
__device__ int   g_cnt[NN];
__device__ int   g_fill[NN];
__device__ int   g_ptr[NN + 1];
__device__ float g_dis[NN];
__device__ __align__(16) uint2 g_csr[EE];   // packed (src, w)
__device__ int   g_bsum[SCAN_NB];
__device__ int   g_boff[SCAN_NB];
__device__ float g_ps1[AGG_NB * HH];
__device__ float g_pq1[AGG_NB * HH];
__device__ float g_mids[STAT_NB * HH];
__device__ float g_midq[STAT_NB * HH];
__device__ float g_bn_a[HH];
__device__ float g_bn_b[HH];
__device__ int   g_goff[GG + 1];
__device__ float g_z[GG * FC1];
// W pre-split to bf16 hi/lo, transposed & packed: [layer][n][k/2] (k-pairs)
__device__ __align__(16) unsigned g_wt2h[3][HH * (HH / 2)];
__device__ __align__(16) unsigned g_wt2l[3][HH * (HH / 2)];
__device__ int   g_tick;      // scanall ticket
__device__ int   g_flag;      // scanall release flag
__device__ int   g_tick2[3];  // stats tickets (per layer)
__device__ int   g_is64;

// ---------------- helpers ----------------
__device__ __forceinline__ int ld_idx(const void* p, long long i, int is64) {
    return is64 ? (int)(((const long long*)p)[i]) : ((const int*)p)[i];
}

// bf16 hi/lo split of two floats, packed into bf16x2 words (low = first elem)
__device__ __forceinline__ unsigned packsplit(float v0, float v1, unsigned* plo) {
    __nv_bfloat16 h0 = __float2bfloat16(v0);
    __nv_bfloat16 h1 = __float2bfloat16(v1);
    float l0f = v0 - __bfloat162float(h0);
    float l1f = v1 - __bfloat162float(h1);
    __nv_bfloat16 l0 = __float2bfloat16(l0f);
    __nv_bfloat16 l1 = __float2bfloat16(l1f);
    *plo = ((unsigned)__bfloat16_as_ushort(l1) << 16) | __bfloat16_as_ushort(l0);
    return ((unsigned)__bfloat16_as_ushort(h1) << 16) | __bfloat16_as_ushort(h0);
}

// ---------------- pre1: zero + counters + dtype detect + W presplit --------
__global__ void k_pre1(const void* eidx, const float* W1, const float* W2,
                       const float* W3) {
    int i = blockIdx.x * blockDim.x + threadIdx.x;
    if (i < NN) { g_cnt[i] = 0; g_fill[i] = 0; }
    if (i == 0) {
        g_tick = 0; g_flag = 0;
        g_tick2[0] = 0; g_tick2[1] = 0; g_tick2[2] = 0;
    }
    if (blockIdx.x == 0) {
        __shared__ int any;
        if (threadIdx.x == 0) any = 0;
        __syncthreads();
        if (((const int*)eidx)[2 * threadIdx.x + 1] != 0) atomicOr(&any, 1);
        __syncthreads();
        if (threadIdx.x == 0) g_is64 = any ? 0 : 1;
    }
    // W bf16 hi/lo presplit, transposed to [n][k/2]: 3 * 128 * 64 pairs
    if (i < 3 * HH * (HH / 2)) {
        int l = i / (HH * (HH / 2));
        int j = i - l * (HH * (HH / 2));
        int n = j >> 6;
        int kk = j & 63;
        const float* Wsrc = (l == 0) ? W1 : (l == 1) ? W2 : W3;
        float w0 = Wsrc[(2 * kk) * HH + n];
        float w1 = Wsrc[(2 * kk + 1) * HH + n];
        unsigned lo;
        unsigned hi = packsplit(w0, w1, &lo);
        g_wt2h[l][n * 64 + kk] = hi;
        g_wt2l[l][n * 64 + kk] = lo;
    }
}

// ---------------- count (edge histogram) + graph bounds ----------------
__global__ void k_count(const void* eidx, const void* batch) {
    int e = blockIdx.x * blockDim.x + threadIdx.x;
    int is64 = g_is64;
    if (e < EE) {
        int d = ld_idx(eidx, (long long)EE + e, is64);
        atomicAdd(&g_cnt[d], 1);
    }
    if (e < NN) {
        int b = ld_idx(batch, e, is64);
        int bn = (e + 1 < NN) ? ld_idx(batch, e + 1, is64) : GG;
        if (e == 0)
            for (int g = 0; g <= b && g <= GG; g++) g_goff[g] = 0;
        int hi = bn < GG ? bn : GG;
        for (int g = b + 1; g <= hi; g++) g_goff[g] = e + 1;
    }
}

// ---------------- single-launch CSR scan (ticket + flag spin) ----------------
__global__ void __launch_bounds__(SCAN_TB) k_scanall() {
    __shared__ int sm[SCAN_TB];
    __shared__ int islast;
    int t = threadIdx.x;
    int b = blockIdx.x;
    int i = b * SCAN_TB + t;
    int c = (i < NN) ? g_cnt[i] : 0;
    sm[t] = c;
    __syncthreads();
    for (int off = 1; off < SCAN_TB; off <<= 1) {
        int v = (t >= off) ? sm[t - off] : 0;
        __syncthreads();
        sm[t] += v;
        __syncthreads();
    }
    int local_ex = sm[t] - c;
    int total = sm[SCAN_TB - 1];
    if (t == 0) {
        g_bsum[b] = total;
        __threadfence();
        islast = (atomicAdd(&g_tick, 1) == SCAN_NB - 1);
    }
    __syncthreads();
    if (islast) {
        int v = (t < SCAN_NB) ? g_bsum[t] : 0;
        __syncthreads();
        sm[t] = v;
        __syncthreads();
        for (int off = 1; off < SCAN_TB; off <<= 1) {
            int u = (t >= off) ? sm[t - off] : 0;
            __syncthreads();
            sm[t] += u;
            __syncthreads();
        }
        if (t < SCAN_NB) g_boff[t] = sm[t] - v;
        __threadfence();
        __syncthreads();
        if (t == 0) atomicExch(&g_flag, 1);
    }
    if (t == 0) {
        while (atomicAdd(&g_flag, 0) == 0) __nanosleep(100);
    }
    __syncthreads();
    __threadfence();
    int ex = local_ex + g_boff[b];
    if (i < NN) {
        g_ptr[i] = ex;
        g_dis[i] = rsqrtf((float)(c + 1));
        if (i == NN - 1) g_ptr[NN] = ex + c;
    }
}

__global__ void k_fill(const void* eidx) {
    int e = blockIdx.x * blockDim.x + threadIdx.x;
    if (e >= EE) return;
    int is64 = g_is64;
    int s = ld_idx(eidx, e, is64);
    int d = ld_idx(eidx, (long long)EE + e, is64);
    int pos = atomicAdd(&g_fill[d], 1);
    float w = g_dis[s] * g_dis[d];
    g_csr[g_ptr[d] + pos] = make_uint2((unsigned)s, __float_as_uint(w));
}

// ------- persistent 3xBF16 GEMM: W resident, double-buffered X prefetch ----
// g_h16u[N,128](fp16) = f(X)[N,128] @ W[128,128]; f = id or BN+ReLU.
// 148 blocks x 512 thr; warps 4(M)x4(N); warp tile 32x32 (2x4 m16n8k16).
#define P_STRIDE 68    /* 64 bf16x2 pairs + pad (uints) */
#define XBUF (2 * 128 * P_STRIDE)
#define GEMM_SMEM ((2 * 128 * P_STRIDE + 2 * XBUF) * 4)   /* ~209 KB */
#define GEMM_TILES ((NN + 127) / 128)
#define GEMM_BLK 148

template <bool BN>
__global__ void __launch_bounds__(512, 1) k_gemm_tc(const float* __restrict__ X,
                                                    const unsigned* __restrict__ Wth,
                                                    const unsigned* __restrict__ Wtl) {
    extern __shared__ unsigned usmem[];
    unsigned* Wh2 = usmem;                      // [128][68]
    unsigned* Wl2 = Wh2 + 128 * P_STRIDE;
    unsigned* Xb  = Wl2 + 128 * P_STRIDE;       // [2][2][128*68]
    int tid = threadIdx.x;
    int b = blockIdx.x;

    int wid = tid >> 5;
    int lane = tid & 31;
    int mwid = wid >> 2;
    int nwid = wid & 3;
    int g = lane >> 2;
    int tg = lane & 3;
    int lr[8], lc4[8];
#pragma unroll
    for (int i = 0; i < 8; i++) {
        int q = i * 512 + tid;
        lr[i] = q >> 5;
        lc4[i] = q & 31;
    }

    // W resident load (once)
#pragma unroll
    for (int i = 0; i < 4; i++) {
        int q = i * 512 + tid;
        int r = q >> 4;
        int c = (q & 15) * 4;
        *(uint4*)(Wh2 + r * P_STRIDE + c) = *(const uint4*)(Wth + r * 64 + c);
        *(uint4*)(Wl2 + r * P_STRIDE + c) = *(const uint4*)(Wtl + r * 64 + c);
    }

#define LOADX(TILE, PF)                                                     \
    do {                                                                    \
        int row0p = (TILE) * 128;                                           \
        _Pragma("unroll") for (int i = 0; i < 8; i++) {                     \
            int gr = row0p + lr[i];                                         \
            PF[i] = make_float4(0.f, 0.f, 0.f, 0.f);                        \
            if (gr < NN) PF[i] = *(const float4*)(X + (size_t)gr * 128 + lc4[i] * 4); \
        }                                                                   \
    } while (0)

#define STOREX(BUF, PF)                                                     \
    do {                                                                    \
        _Pragma("unroll") for (int i = 0; i < 8; i++) {                     \
            float4 v = PF[i];                                               \
            if (BN) {                                                       \
                int ch = lc4[i] * 4;                                        \
                v.x = fmaxf(g_bn_a[ch + 0] * v.x + g_bn_b[ch + 0], 0.f);    \
                v.y = fmaxf(g_bn_a[ch + 1] * v.y + g_bn_b[ch + 1], 0.f);    \
                v.z = fmaxf(g_bn_a[ch + 2] * v.z + g_bn_b[ch + 2], 0.f);    \
                v.w = fmaxf(g_bn_a[ch + 3] * v.w + g_bn_b[ch + 3], 0.f);    \
            }                                                               \
            unsigned lo0, lo1;                                              \
            unsigned hi0 = packsplit(v.x, v.y, &lo0);                       \
            unsigned hi1 = packsplit(v.z, v.w, &lo1);                       \
            int o = lr[i] * P_STRIDE + lc4[i] * 2;                          \
            (BUF)[o] = hi0; (BUF)[o + 1] = hi1;                             \
            (BUF)[o + 128 * P_STRIDE] = lo0;                                \
            (BUF)[o + 128 * P_STRIDE + 1] = lo1;                            \
        }                                                                   \
    } while (0)

#define MMA16(A0, A1, A2, A3, B0, B1, C)                                \
    asm volatile(                                                       \
        "mma.sync.aligned.m16n8k16.row.col.f32.bf16.bf16.f32 "          \
        "{%0,%1,%2,%3}, {%4,%5,%6,%7}, {%8,%9}, {%0,%1,%2,%3};"         \
        : "+f"(C[0]), "+f"(C[1]), "+f"(C[2]), "+f"(C[3])                \
        : "r"(A0), "r"(A1), "r"(A2), "r"(A3), "r"(B0), "r"(B1))

    // prologue: tile b into buf 0
    {
        float4 pf[8];
        LOADX(b, pf);
        STOREX(Xb, pf);
    }
    __syncthreads();

    int nt = 0;
    for (int tile = b; tile < GEMM_TILES; tile += GEMM_BLK, nt++) {
        int cur = nt & 1;
        unsigned* Xh2 = Xb + cur * XBUF;
        unsigned* Xl2 = Xh2 + 128 * P_STRIDE;
        int row0 = tile * 128;
        int next = tile + GEMM_BLK;

        float4 pf[8];
        if (next < GEMM_TILES) LOADX(next, pf);

        float acc[2][4][4];
#pragma unroll
        for (int mi = 0; mi < 2; mi++)
#pragma unroll
            for (int ni = 0; ni < 4; ni++)
#pragma unroll
                for (int j = 0; j < 4; j++) acc[mi][ni][j] = 0.f;

#pragma unroll
        for (int kp = 0; kp < 64; kp += 8) {
            unsigned ah[2][4], al[2][4];
#pragma unroll
            for (int mi = 0; mi < 2; mi++) {
                int rb = mwid * 32 + mi * 16;
                int o0 = (rb + g) * P_STRIDE + kp + tg;
                int o1 = (rb + g + 8) * P_STRIDE + kp + tg;
                ah[mi][0] = Xh2[o0];
                ah[mi][1] = Xh2[o1];
                ah[mi][2] = Xh2[o0 + 4];
                ah[mi][3] = Xh2[o1 + 4];
                al[mi][0] = Xl2[o0];
                al[mi][1] = Xl2[o1];
                al[mi][2] = Xl2[o0 + 4];
                al[mi][3] = Xl2[o1 + 4];
            }
#pragma unroll
            for (int ni = 0; ni < 4; ni++) {
                int cb = nwid * 32 + ni * 8;
                int o = (cb + g) * P_STRIDE + kp + tg;
                unsigned bh0 = Wh2[o];
                unsigned bh1 = Wh2[o + 4];
                unsigned bl0 = Wl2[o];
                unsigned bl1 = Wl2[o + 4];
#pragma unroll
                for (int mi = 0; mi < 2; mi++) {
                    MMA16(ah[mi][0], ah[mi][1], ah[mi][2], ah[mi][3],
                          bh0, bh1, acc[mi][ni]);
                    MMA16(ah[mi][0], ah[mi][1], ah[mi][2], ah[mi][3],
                          bl0, bl1, acc[mi][ni]);
                    MMA16(al[mi][0], al[mi][1], al[mi][2], al[mi][3],
                          bh0, bh1, acc[mi][ni]);
                }
            }
        }

        if (next < GEMM_TILES) STOREX(Xb + (cur ^ 1) * XBUF, pf);

        // epilogue: fp16 pairs
#pragma unroll
        for (int mi = 0; mi < 2; mi++) {
#pragma unroll
            for (int ni = 0; ni < 4; ni++) {
                int col = nwid * 32 + ni * 8 + tg * 2;
                int r1 = row0 + mwid * 32 + mi * 16 + g;
                int r2 = r1 + 8;
                if (r1 < NN) {
                    __half2 h = __floats2half2_rn(acc[mi][ni][0], acc[mi][ni][1]);
                    g_h16u[(size_t)r1 * 64 + (col >> 1)] = *(unsigned*)&h;
                }
                if (r2 < NN) {
                    __half2 h = __floats2half2_rn(acc[mi][ni][2], acc[mi][ni][3]);
                    g_h16u[(size_t)r2 * 64 + (col >> 1)] = *(unsigned*)&h;
                }
            }
        }
        __syncthreads();
    }
#undef MMA16
#undef LOADX
#undef STOREX
}

// ---------------- aggregation (fp16 gather) + fused BN partial stats --------
__global__ void __launch_bounds__(256) k_agg(const float* __restrict__ bias) {
    __shared__ float ps[8][HH];
    __shared__ float pq[8][HH];
    int w = threadIdx.x >> 5;
    int lane = threadIdx.x & 31;
    int d = blockIdx.x * 8 + w;   // NN = 6250*8 exact

    const uint2* Hv = (const uint2*)g_h16u;
    float sd = g_dis[d];
    float ws = sd * sd;
    uint2 u = Hv[(size_t)d * 32 + lane];
    float2 f0 = __half22float2(*(__half2*)&u.x);
    float2 f1 = __half22float2(*(__half2*)&u.y);
    float4 acc = make_float4(f0.x * ws, f0.y * ws, f1.x * ws, f1.y * ws);

    int beg = g_ptr[d], end = g_ptr[d + 1];
    int j = beg;
    for (; j + 4 <= end; j += 4) {
        uint2 e0 = g_csr[j + 0], e1 = g_csr[j + 1];
        uint2 e2 = g_csr[j + 2], e3 = g_csr[j + 3];
        float w0 = __uint_as_float(e0.y), w1 = __uint_as_float(e1.y);
        float w2 = __uint_as_float(e2.y), w3 = __uint_as_float(e3.y);
        uint2 u0 = Hv[(size_t)e0.x * 32 + lane];
        uint2 u1 = Hv[(size_t)e1.x * 32 + lane];
        uint2 u2 = Hv[(size_t)e2.x * 32 + lane];
        uint2 u3 = Hv[(size_t)e3.x * 32 + lane];
        float2 a0, c0;
        a0 = __half22float2(*(__half2*)&u0.x); c0 = __half22float2(*(__half2*)&u0.y);
        acc.x += a0.x * w0; acc.y += a0.y * w0; acc.z += c0.x * w0; acc.w += c0.y * w0;
        a0 = __half22float2(*(__half2*)&u1.x); c0 = __half22float2(*(__half2*)&u1.y);
        acc.x += a0.x * w1; acc.y += a0.y * w1; acc.z += c0.x * w1; acc.w += c0.y * w1;
        a0 = __half22float2(*(__half2*)&u2.x); c0 = __half22float2(*(__half2*)&u2.y);
        acc.x += a0.x * w2; acc.y += a0.y * w2; acc.z += c0.x * w2; acc.w += c0.y * w2;
        a0 = __half22float2(*(__half2*)&u3.x); c0 = __half22float2(*(__half2*)&u3.y);
        acc.x += a0.x * w3; acc.y += a0.y * w3; acc.z += c0.x * w3; acc.w += c0.y * w3;
    }
    for (; j < end; j++) {
        uint2 e = g_csr[j];
        float wj = __uint_as_float(e.y);
        uint2 us = Hv[(size_t)e.x * 32 + lane];
        float2 a0 = __half22float2(*(__half2*)&us.x);
        float2 c0 = __half22float2(*(__half2*)&us.y);
        acc.x += a0.x * wj; acc.y += a0.y * wj; acc.z += c0.x * wj; acc.w += c0.y * wj;
    }
    float4 b4 = ((const float4*)bias)[lane];
    acc.x += b4.x; acc.y += b4.y; acc.z += b4.z; acc.w += b4.w;
    ((float4*)(g_agg + (size_t)d * HH))[lane] = acc;

    int c0i = 4 * lane;
    ps[w][c0i + 0] = acc.x; ps[w][c0i + 1] = acc.y;
    ps[w][c0i + 2] = acc.z; ps[w][c0i + 3] = acc.w;
    pq[w][c0i + 0] = acc.x * acc.x; pq[w][c0i + 1] = acc.y * acc.y;
    pq[w][c0i + 2] = acc.z * acc.z; pq[w][c0i + 3] = acc.w * acc.w;
    __syncthreads();
    int t = threadIdx.x;
    if (t < HH) {
        float s = 0.f;
#pragma unroll
        for (int i = 0; i < 8; i++) s += ps[i][t];
        g_ps1[blockIdx.x * HH + t] = s;
    } else {
        int c = t - HH;
        float s = 0.f;
#pragma unroll
        for (int i = 0; i < 8; i++) s += pq[i][c];
        g_pq1[blockIdx.x * HH + c] = s;
    }
}

// ---------------- BN stats: one launch (mid + ticketed final) ----------------
#define ROWS_PER_STAT 49  /* 128*49 = 6272 >= 6250 */
__global__ void __launch_bounds__(256) k_stats(int which,
                                               const float* __restrict__ gam,
                                               const float* __restrict__ bet) {
    __shared__ int islast;
    int b = blockIdx.x;
    int t = threadIdx.x;
    int c = t & (HH - 1);
    int isq = t >> 7;
    const float* src = isq ? g_pq1 : g_ps1;
    float s = 0.f;
    int r0 = b * ROWS_PER_STAT;
    int r1 = r0 + ROWS_PER_STAT;
    if (r1 > AGG_NB) r1 = AGG_NB;
    for (int r = r0; r < r1; r++) s += src[r * HH + c];
    if (isq) g_midq[b * HH + c] = s;
    else     g_mids[b * HH + c] = s;
    __threadfence();
    if (t == 0) islast = (atomicAdd(&g_tick2[which], 1) == STAT_NB - 1);
    __syncthreads();
    if (!islast) return;
    if (t < HH) {
        float su = 0.f, q = 0.f;
        for (int b2 = 0; b2 < STAT_NB; b2++) {
            su += g_mids[b2 * HH + t];
            q  += g_midq[b2 * HH + t];
        }
        float m = su / (float)NN;
        float var = q / (float)NN - m * m;
        float a = gam[t] * rsqrtf(var + EPSBN);
        g_bn_a[t] = a;
        g_bn_b[t] = bet[t] - m * a;
    }
}

// ---------------- pool (BN3+ReLU fused) + FC1, one kernel ----------------
__global__ void __launch_bounds__(128) k_poolfc1(const float* __restrict__ Wf,
                                                 const float* __restrict__ bf) {
    __shared__ float pooled[HH];
    int gI = blockIdx.x;
    int c = threadIdx.x;
    int beg = g_goff[gI], end = g_goff[gI + 1];
    float a = g_bn_a[c], b = g_bn_b[c];
    float acc = 0.f;
    for (int r = beg; r < end; r++) {
        float v = g_agg[(size_t)r * HH + c];
        acc += fmaxf(a * v + b, 0.f);
    }
    float cnt = (float)(end - beg);
    pooled[c] = acc / fmaxf(cnt, 1.f);
    __syncthreads();
    if (c < FC1) {
        float s = bf[c];
#pragma unroll 8
        for (int k = 0; k < HH; k++) s += pooled[k] * Wf[k * FC1 + c];
        g_z[gI * FC1 + c] = s;
    }
}

// ---------------- head: fc BN stats + fc2, one block ----------------
__global__ void __launch_bounds__(512) k_head(const float* __restrict__ gam,
                                              const float* __restrict__ bet,
                                              const float* __restrict__ W2f,
                                              const float* __restrict__ b2f,
                                              float* __restrict__ out) {
    __shared__ float fa[FC1], fb[FC1];
    int t = threadIdx.x;
    if (t < FC1) {
        float s = 0.f, q = 0.f;
#pragma unroll 4
        for (int r = 0; r < GG; r++) {
            float v = g_z[r * FC1 + t];
            s += v;
            q += v * v;
        }
        float m = s / (float)GG;
        float var = q / (float)GG - m * m;
        float a = gam[t] * rsqrtf(var + EPSBN);
        fa[t] = a;
        fb[t] = bet[t] - m * a;
    }
    __syncthreads();
    if (t < GG) {
        float s = b2f[0];
#pragma unroll 8
        for (int c = 0; c < FC1; c++) {
            float v = g_z[t * FC1 + c];
            v = fmaxf(fa[c] * v + fb[c], 0.f);
            s += v * W2f[c];
        }
        out[t] = s;
    }
}

// ---------------- launch ----------------
extern "C" void kernel_launch(void* const* d_in, const int* in_sizes, int n_in,
                              void* d_out, int out_size) {
    const float* x    = (const float*)d_in[0];
    const void*  eidx = d_in[1];
    const void*  batc = d_in[2];
    const float* W1 = (const float*)d_in[3];
    const float* b1 = (const float*)d_in[4];
    const float* g1 = (const float*)d_in[5];
    const float* be1 = (const float*)d_in[6];
    const float* W2 = (const float*)d_in[7];
    const float* b2 = (const float*)d_in[8];
    const float* g2 = (const float*)d_in[9];
    const float* be2 = (const float*)d_in[10];
    const float* W3 = (const float*)d_in[11];
    const float* b3 = (const float*)d_in[12];
    const float* g3 = (const float*)d_in[13];
    const float* be3 = (const float*)d_in[14];
    const float* fcW1 = (const float*)d_in[15];
    const float* fcb1 = (const float*)d_in[16];
    const float* fcg1 = (const float*)d_in[17];
    const float* fcbe1 = (const float*)d_in[18];
    const float* fcW2 = (const float*)d_in[19];
    const float* fcb2 = (const float*)d_in[20];
    float* out = (float*)d_out;

    float* pagg = nullptr;
    unsigned *pwth = nullptr, *pwtl = nullptr;
    cudaGetSymbolAddress((void**)&pagg, g_agg);
    cudaGetSymbolAddress((void**)&pwth, g_wt2h);
    cudaGetSymbolAddress((void**)&pwtl, g_wt2l);

    const int TB = 256;
    const int WSZ = HH * (HH / 2);   // uints per layer in g_wt2h/l

    static int init_done = 0;
    static cudaStream_t s2;
    static cudaEvent_t ev1, ev2;
    if (!init_done) {
        cudaFuncSetAttribute(k_gemm_tc<false>,
                             cudaFuncAttributeMaxDynamicSharedMemorySize, GEMM_SMEM);
        cudaFuncSetAttribute(k_gemm_tc<true>,
                             cudaFuncAttributeMaxDynamicSharedMemorySize, GEMM_SMEM);
        cudaStreamCreateWithFlags(&s2, cudaStreamNonBlocking);
        cudaEventCreateWithFlags(&ev1, cudaEventDisableTiming);
        cudaEventCreateWithFlags(&ev2, cudaEventDisableTiming);
        init_done = 1;
    }

    // preprocessing chain; layer-1 GEMM forked onto s2 (needs only pre1 + x)
    k_pre1<<<SCAN_NB, TB>>>(eidx, W1, W2, W3);
    cudaEventRecord(ev1, 0);
    cudaStreamWaitEvent(s2, ev1, 0);
    k_gemm_tc<false><<<GEMM_BLK, 512, GEMM_SMEM, s2>>>(x, pwth, pwtl);
    cudaEventRecord(ev2, s2);

    k_count<<<(EE + TB - 1) / TB, TB>>>(eidx, batc);
    k_scanall<<<SCAN_NB, SCAN_TB>>>();
    k_fill<<<(EE + TB - 1) / TB, TB>>>(eidx);
    cudaStreamWaitEvent(0, ev2, 0);

    // layer 1
    k_agg<<<AGG_NB, TB>>>(b1);
    k_stats<<<STAT_NB, TB>>>(0, g1, be1);
    // layer 2
    k_gemm_tc<true><<<GEMM_BLK, 512, GEMM_SMEM>>>(pagg, pwth + WSZ, pwtl + WSZ);
    k_agg<<<AGG_NB, TB>>>(b2);
    k_stats<<<STAT_NB, TB>>>(1, g2, be2);
    // layer 3
    k_gemm_tc<true><<<GEMM_BLK, 512, GEMM_SMEM>>>(pagg, pwth + 2 * WSZ, pwtl + 2 * WSZ);
    k_agg<<<AGG_NB, TB>>>(b3);
    k_stats<<<STAT_NB, TB>>>(2, g3, be3);

    // pool+fc1, then head
    k_poolfc1<<<GG, 128>>>(fcW1, fcb1);
    k_head<<<1, 512>>>(fcg1, fcbe1, fcW2, fcb2, out);
}